// round 15
// baseline (speedup 1.0000x reference)
#include <cuda_runtime.h>
#include <math.h>
#include <stdint.h>

// ---------------- model constants ----------------
#define NBB 32
#define LSEQ 512
#define EIN 512
#define NMARK 4
#define DM 512
#define HH 8
#define DFF 2048
#define NL 2
#define NHASH 4
#define NTOK 516
#define TP 520
#define DHD 64
#define NB 130
#define NBINS 520
#define NCH 520
#define BHN 256
#define MROWS (NBB*TP)   // 16640
#define MTOK (NBB*NTOK)  // 16512
#define KST 68

// GEMM tiling: stage = [A raw 16KB | B pairs 32KB]
#define STAGES 2
#define A_CHUNK 16384
#define B_CHUNK 32768
#define STAGE_BYTES (A_CHUNK + B_CHUNK)  // 49152
#define GEMM_SMEM (STAGES*STAGE_BYTES)   // 98304 -> 2 CTAs/SM

// weight scratch offsets (element units; pair index = 2*off)
#define OFF_EMB   0
#define OFF_QKV0  262144
#define OFF_QKV1  786432
#define OFF_O0    1310720
#define OFF_O1    1572864
#define OFF_C1_0  1835008
#define OFF_C1_1  2883584
#define OFF_C2_0  3932160
#define OFF_C2_1  4980736
#define GW_TOT    6029312

// ---------------- device scratch ----------------
__device__ float g_x[MROWS * DM];
__device__ float g_qk[MROWS * DM];
__device__ float g_v[MROWS * DM];
__device__ float g_attn[MROWS * DM];
__device__ float g_y[MROWS * DM];
__device__ float g_h[MROWS * DFF];
__device__ float g_wp[GW_TOT * 2];       // weights as interleaved (hi,lo) pairs
__device__ float g_ohash[BHN * NHASH * TP * DHD];
__device__ float g_lse[BHN * NHASH * TP];
__device__ int   g_bin[BHN * NHASH * TP];
__device__ int   g_stick[BHN * NHASH * TP];
__device__ float g_mean[NBB * EIN];
__device__ float g_std[NBB * EIN];
__device__ float g_dec[NBB];
// compact layer-2 buffers (rows 0..31 real, 32..127 zero pad)
__device__ float g_cattn[128 * DM];
__device__ float g_cx[128 * DM];
__device__ float g_cy[128 * DM];
__device__ float g_ch[128 * DFF];

// ---------------- helpers ----------------
__device__ __forceinline__ uint32_t s2u(const void* p) {
    uint32_t a;
    asm("{ .reg .u64 t; cvta.to.shared.u64 t, %1; cvt.u32.u64 %0, t; }" : "=r"(a) : "l"(p));
    return a;
}
__device__ __forceinline__ uint32_t swz(uint32_t x) { return x ^ ((x >> 3) & 0x70); }
__device__ __forceinline__ uint32_t lds_u(uint32_t a) {
    uint32_t v;
    asm volatile("ld.shared.b32 %0, [%1];" : "=r"(v) : "r"(a));
    return v;
}
__device__ __forceinline__ void lds_v2(uint32_t a, uint32_t& x, uint32_t& y) {
    asm volatile("ld.shared.v2.b32 {%0,%1}, [%2];" : "=r"(x), "=r"(y) : "r"(a));
}
// split fp32 into tf32 hi + tf32 lo (x ~= hi + lo)
__device__ __forceinline__ void split_tf32(uint32_t xu, uint32_t& hi, uint32_t& lo) {
    float x = __uint_as_float(xu);
    uint32_t h;
    asm("cvt.rna.tf32.f32 %0, %1;" : "=r"(h) : "f"(x));
    float lf = x - __uint_as_float(h);
    uint32_t l;
    asm("cvt.rna.tf32.f32 %0, %1;" : "=r"(l) : "f"(lf));
    hi = h; lo = l;
}
__device__ __forceinline__ void cpwait(int n) {
    if (n <= 0) asm volatile("cp.async.wait_group 0;" ::: "memory");
    else        asm volatile("cp.async.wait_group 1;" ::: "memory");
}
// stage = [A raw (SW128) | B pairs (8B-swizzled)], k-chunk 32
__device__ __forceinline__ void ld_chunk(const float* __restrict__ A,
                                         const float* __restrict__ Wp, int K,
                                         int bm, int bn, int c, uint32_t stg, int tid) {
    // A: 128 rows x 32 f32, 1024 granules of 16B
#pragma unroll
    for (int it = 0; it < 4; ++it) {
        int idx = it * 256 + tid;
        int r = idx >> 3, g = idx & 7;
        const float* src = A + (size_t)(bm + r) * K + (c << 5) + (g << 2);
        uint32_t dst = stg + swz((uint32_t)(r * 128 + g * 16));
        asm volatile("cp.async.cg.shared.global [%0], [%1], 16;" :: "r"(dst), "l"(src));
    }
    // B pairs: 128 rows x 32 pairs (8B), 2048 granules of 16B (2 pairs each)
    uint32_t stgB = stg + A_CHUNK;
#pragma unroll
    for (int it = 0; it < 8; ++it) {
        int idx = it * 256 + tid;
        int r = idx >> 4, g = idx & 15;
        const float* src = Wp + (size_t)(bn + r) * (2 * K) + (c << 6) + (g << 2);
        uint32_t sc = (uint32_t)((2 * g) ^ ((r & 7) << 2));
        uint32_t dst = stgB + (uint32_t)r * 256 + sc * 8;
        asm volatile("cp.async.cg.shared.global [%0], [%1], 16;" :: "r"(dst), "l"(src));
    }
    asm volatile("cp.async.commit_group;" ::: "memory");
}

#define MMA_TF32(cc, a0, a1, a2, a3, b0, b1) \
    asm("mma.sync.aligned.m16n8k8.row.col.f32.tf32.tf32.f32 " \
        "{%0,%1,%2,%3}, {%4,%5,%6,%7}, {%8,%9}, {%0,%1,%2,%3};" \
        : "+f"((cc)[0]), "+f"((cc)[1]), "+f"((cc)[2]), "+f"((cc)[3]) \
        : "r"(a0), "r"(a1), "r"(a2), "r"(a3), "r"(b0), "r"(b1))

// ---------------- split-tf32 (3xTF32) tensor-core GEMM ----------------
// C[M,N] = A[M,K] * W[N,K]^T (+bias)(+relu); W as interleaved (hi,lo) pair plane.
// M,N mult of 128, K mult of 32. flags: 1 = relu, 2 = row remap 516->520.
// Columns >= nsplit are routed to C2 (at col-nsplit); both outputs have leading dim ldc.
__global__ void __launch_bounds__(256) gemm_3xtf32(
    const float* __restrict__ A, const float* __restrict__ Wpair,
    const float* __restrict__ bias, float* __restrict__ C, float* __restrict__ C2,
    int K, int N, int ldc, int nsplit, int flags)
{
    extern __shared__ char smem[];
    uint32_t sb = s2u(smem);
    int tid = threadIdx.x, wid = tid >> 5, lane = tid & 31;
    int gid = lane >> 2, tig = lane & 3;
    int warp_m = wid & 3, warp_n = wid >> 2;        // 4 x 2 warp layout
    int bm = blockIdx.y * 128, bn = blockIdx.x * 128;
    const int NC = K >> 5;
    const uint32_t gmask = (uint32_t)gid << 4;      // SW128 A swizzle mask
    const uint32_t bxor = (uint32_t)gid << 2;       // B pair-column swizzle

    float acc[2][8][4];
#pragma unroll
    for (int m = 0; m < 2; ++m)
#pragma unroll
        for (int n = 0; n < 8; ++n)
#pragma unroll
            for (int q = 0; q < 4; ++q) acc[m][n][q] = 0.f;

#pragma unroll
    for (int p = 0; p < STAGES; ++p)
        ld_chunk(A, Wpair, K, bm, bn, p, sb + p * STAGE_BYTES, tid);

    for (int c = 0; c < NC; ++c) {
        int s = c & 1;
        int pend = NC - 1 - c; if (pend > STAGES - 1) pend = STAGES - 1;
        cpwait(pend);
        __syncthreads();
        uint32_t aA = sb + s * STAGE_BYTES;
        uint32_t aB = aA + A_CHUNK;
#pragma unroll
        for (int kq = 0; kq < 4; ++kq) {
            uint32_t k4 = (uint32_t)kq * 32;
            uint32_t kx0 = (k4 ^ gmask) + (uint32_t)tig * 4;
            uint32_t kx1 = ((k4 + 16) ^ gmask) + (uint32_t)tig * 4;
            // B pair columns (8B units) for this kq
            uint32_t sc0 = (uint32_t)(((kq << 3) + tig) ^ bxor) * 8;
            uint32_t sc1 = (uint32_t)(((kq << 3) + 4 + tig) ^ bxor) * 8;
            uint32_t ah[2][4], al[2][4];
#pragma unroll
            for (int m = 0; m < 2; ++m) {
                uint32_t r0 = aA + (uint32_t)(warp_m * 32 + m * 16 + gid) * 128;
                uint32_t r1 = r0 + 8 * 128;
                split_tf32(lds_u(r0 + kx0), ah[m][0], al[m][0]);
                split_tf32(lds_u(r1 + kx0), ah[m][1], al[m][1]);
                split_tf32(lds_u(r0 + kx1), ah[m][2], al[m][2]);
                split_tf32(lds_u(r1 + kx1), ah[m][3], al[m][3]);
            }
#pragma unroll
            for (int n = 0; n < 8; ++n) {
                uint32_t rb = aB + (uint32_t)(warp_n * 64 + n * 8 + gid) * 256;
                uint32_t bh0, bl0, bh1, bl1;
                lds_v2(rb + sc0, bh0, bl0);
                lds_v2(rb + sc1, bh1, bl1);
#pragma unroll
                for (int m = 0; m < 2; ++m) {
                    MMA_TF32(acc[m][n], al[m][0], al[m][1], al[m][2], al[m][3], bh0, bh1);
                    MMA_TF32(acc[m][n], ah[m][0], ah[m][1], ah[m][2], ah[m][3], bl0, bl1);
                    MMA_TF32(acc[m][n], ah[m][0], ah[m][1], ah[m][2], ah[m][3], bh0, bh1);
                }
            }
        }
        __syncthreads();
        if (c + STAGES < NC)
            ld_chunk(A, Wpair, K, bm, bn, c + STAGES, sb + s * STAGE_BYTES, tid);
    }

    // epilogue
    float* Ct = C;
    int cb = bn;
    if (bn >= nsplit) { Ct = C2; cb = bn - nsplit; }
#pragma unroll
    for (int m = 0; m < 2; ++m) {
        int r0 = bm + warp_m * 32 + m * 16 + gid;
        int r1 = r0 + 8;
        int o0 = r0, o1 = r1;
        if (flags & 2) {
            int bb0 = r0 / 516; o0 = bb0 * 520 + (r0 - bb0 * 516);
            int bb1 = r1 / 516; o1 = bb1 * 520 + (r1 - bb1 * 516);
        }
#pragma unroll
        for (int n = 0; n < 8; ++n) {
            int cn0 = bn + warp_n * 64 + n * 8 + tig * 2;   // original col (bias index)
            int cnl = cb + warp_n * 64 + n * 8 + tig * 2;   // routed col
            float bx = 0.f, by = 0.f;
            if (bias) { float2 bv = *(const float2*)(bias + cn0); bx = bv.x; by = bv.y; }
            float v0 = acc[m][n][0] + bx, v1 = acc[m][n][1] + by;
            float v2 = acc[m][n][2] + bx, v3 = acc[m][n][3] + by;
            if (flags & 1) {
                v0 = fmaxf(v0, 0.f); v1 = fmaxf(v1, 0.f);
                v2 = fmaxf(v2, 0.f); v3 = fmaxf(v3, 0.f);
            }
            *(float2*)(Ct + (size_t)o0 * ldc + cnl) = make_float2(v0, v1);
            *(float2*)(Ct + (size_t)o1 * ldc + cnl) = make_float2(v2, v3);
        }
    }
}

// ---------------- weight splitting into interleaved pairs (once) ----------------
__global__ void splitw_kernel(const float* __restrict__ s, float* __restrict__ d, int n2) {
    int i = blockIdx.x * 256 + threadIdx.x;
    if (i >= n2) return;
    float2 v = ((const float2*)s)[i];
    uint32_t h0, l0, h1, l1;
    split_tf32(__float_as_uint(v.x), h0, l0);
    split_tf32(__float_as_uint(v.y), h1, l1);
    ((float4*)d)[i] = make_float4(__uint_as_float(h0), __uint_as_float(l0),
                                  __uint_as_float(h1), __uint_as_float(l1));
}

// ---------------- RevIN + tokenization ----------------
__global__ void tok_stats_kernel(const float* __restrict__ xe) {
    int b = blockIdx.y;
    int tx = threadIdx.x, ty = threadIdx.y;
    int e = blockIdx.x * 32 + tx;
    const float* p = xe + (size_t)b * LSEQ * EIN + e;
    float s = 0.f, s2 = 0.f;
    for (int l = ty; l < LSEQ; l += 8) {
        float v = p[(size_t)l * EIN];
        s += v; s2 += v * v;
    }
    __shared__ float sh[8][32], sh2[8][32], shm[32], shr[32];
    sh[ty][tx] = s; sh2[ty][tx] = s2;
    __syncthreads();
    if (ty == 0) {
        float ts = 0.f, ts2 = 0.f;
        for (int r = 0; r < 8; ++r) { ts += sh[r][tx]; ts2 += sh2[r][tx]; }
        float m = ts * (1.f / 512.f);
        float var = ts2 * (1.f / 512.f) - m * m;
        if (var < 0.f) var = 0.f;
        float sd = sqrtf(var + 1e-5f);
        g_mean[b * EIN + e] = m;
        g_std[b * EIN + e] = sd;
        shm[tx] = m; shr[tx] = 1.f / sd;
    }
    __syncthreads();
    float m = shm[tx], r = shr[tx];
    float* orow = g_attn + (size_t)(b * NTOK + e) * LSEQ;
    for (int l = ty; l < LSEQ; l += 8)
        orow[l] = (p[(size_t)l * EIN] - m) * r;
}

__global__ void marks_kernel(const float* __restrict__ xm) {
    int idx = blockIdx.x * 256 + threadIdx.x;
    if (idx >= NBB * NMARK * LSEQ) return;
    int b = idx / (NMARK * LSEQ);
    int rem = idx - b * NMARK * LSEQ;
    int j = rem / LSEQ, l = rem - j * LSEQ;
    g_attn[(size_t)(b * NTOK + EIN + j) * LSEQ + l] =
        xm[((size_t)b * LSEQ + l) * NMARK + j];
}

__global__ void zeropad_kernel() {
    int idx = blockIdx.x * 256 + threadIdx.x;
    if (idx >= NBB * 4 * DM) return;
    int b = idx / (4 * DM);
    int rem = idx - b * 4 * DM;
    int j = rem / DM, d = rem - j * DM;
    g_x[(size_t)(b * TP + NTOK + j) * DM + d] = 0.f;
}

// ---------------- LSH hashing (8 t per warp, register-blocked) ----------------
__global__ void hash_kernel(const float* __restrict__ rotl) {
    int h = blockIdx.x;
    int bh = blockIdx.y;
    int b = bh >> 3, head = bh & 7;
    __shared__ float rs[65 * 64];          // rs[f*65 + i]
    __shared__ float sq[8][8][64];         // [warp][j][f]
    int tid = threadIdx.x;
    for (int idx = tid; idx < 65 * 64; idx += 256) {
        int f = idx / 65, i = idx - f * 65;
        rs[idx] = rotl[(size_t)f * (NHASH * 65) + h * 65 + i];
    }
    __syncthreads();
    int w = tid >> 5, lane = tid & 31;
    for (int t8 = w; t8 < 65; t8 += 8) {
        int t0 = t8 * 8;
        for (int idx = lane; idx < 128; idx += 32) {
            int j = idx >> 4, f4 = idx & 15;
            const float4* qrow = (const float4*)(g_qk + (size_t)(b * TP + t0 + j) * DM + head * DHD);
            *(float4*)&sq[w][j][f4 * 4] = qrow[f4];
        }
        __syncwarp();
        float a0[8], a1[8], a2[8];
#pragma unroll
        for (int j = 0; j < 8; ++j) { a0[j] = 0.f; a1[j] = 0.f; a2[j] = 0.f; }
#pragma unroll 4
        for (int f4 = 0; f4 < 16; ++f4) {
            float4 q[8];
#pragma unroll
            for (int j = 0; j < 8; ++j) q[j] = *(const float4*)&sq[w][j][f4 * 4];
#pragma unroll
            for (int ff = 0; ff < 4; ++ff) {
                int f = f4 * 4 + ff;
                float r0 = rs[f * 65 + lane];
                float r1 = rs[f * 65 + lane + 32];
                float r2 = rs[f * 65 + 64];
#pragma unroll
                for (int j = 0; j < 8; ++j) {
                    float qv = (ff == 0) ? q[j].x : (ff == 1) ? q[j].y : (ff == 2) ? q[j].z : q[j].w;
                    a0[j] += qv * r0;
                    a1[j] += qv * r1;
                    a2[j] += qv * r2;
                }
            }
        }
#pragma unroll
        for (int j = 0; j < 8; ++j) {
            float best = a0[j]; int bidx = lane;
            float n0 = -a0[j];
            if (n0 > best || (n0 == best && lane + 65 < bidx)) { best = n0; bidx = lane + 65; }
            float d1 = a1[j]; int i1 = lane + 32;
            if (d1 > best || (d1 == best && i1 < bidx)) { best = d1; bidx = i1; }
            float n1 = -d1;
            if (n1 > best || (n1 == best && i1 + 65 < bidx)) { best = n1; bidx = i1 + 65; }
            if (lane == 0) {
                float d2 = a2[j];
                if (d2 > best || (d2 == best && 64 < bidx)) { best = d2; bidx = 64; }
                float n2 = -d2;
                if (n2 > best || (n2 == best && 129 < bidx)) { best = n2; bidx = 129; }
            }
            for (int off = 16; off; off >>= 1) {
                float ov = __shfl_xor_sync(0xffffffffu, best, off);
                int oi  = __shfl_xor_sync(0xffffffffu, bidx, off);
                if (ov > best || (ov == best && oi < bidx)) { best = ov; bidx = oi; }
            }
            if (lane == 0) g_bin[(bh * NHASH + h) * TP + t0 + j] = bidx + h * NB;
        }
        __syncwarp();
    }
}

// ---------------- stable counting sort ----------------
__global__ void sort_kernel() {
    int bh = blockIdx.x;
    int tid = threadIdx.x;
    __shared__ int cnt[NBINS], off[NBINS];
    for (int i = tid; i < NBINS; i += 256) cnt[i] = 0;
    __syncthreads();
    for (int i = tid; i < NHASH * TP; i += 256)
        atomicAdd(&cnt[g_bin[bh * (NHASH * TP) + i]], 1);
    __syncthreads();
    if (tid < 32) {
        int carry = 0;
        for (int c = 0; c < NBINS; c += 32) {
            int idx = c + tid;
            int v = (idx < NBINS) ? cnt[idx] : 0;
            int own = v;
            for (int d = 1; d < 32; d <<= 1) {
                int t2 = __shfl_up_sync(0xffffffffu, v, d);
                if (tid >= d) v += t2;
            }
            if (idx < NBINS) off[idx] = (v - own) + carry;
            carry += __shfl_sync(0xffffffffu, v, 31);
        }
    }
    __syncthreads();
    int w = tid >> 5, lane = tid & 31;
    if (w < NHASH) {
        for (int base = 0; base < TP; base += 32) {
            int pos = base + lane;
            bool act = pos < TP;
            unsigned mask = __ballot_sync(0xffffffffu, act);
            if (act) {
                int bin = g_bin[bh * (NHASH * TP) + w * TP + pos];
                unsigned peers = __match_any_sync(mask, bin);
                int leader = __ffs(peers) - 1;
                int rank = __popc(peers & ((1u << lane) - 1));
                int baseoff = 0;
                if (lane == leader) baseoff = atomicAdd(&off[bin], __popc(peers));
                baseoff = __shfl_sync(peers, baseoff, leader);
                g_stick[bh * (NHASH * TP) + baseoff + rank] = w * TP + pos;
            }
            __syncwarp();
        }
    }
}

// ---------------- chunked LSH attention ----------------
__global__ void attn_kernel(int only_pos) {
    int bh = blockIdx.x;
    int b = bh >> 3, head = bh & 7;
    int tid = threadIdx.x, w = tid >> 5, lane = tid & 31;
    __shared__ float sk[8][8 * KST];
    __shared__ float sv[8][8 * KST];
    __shared__ int   sfull[8][8];
    __shared__ float srn[8][8];
    const int sbase = bh * (NHASH * TP);

    for (int c = w + 8 * blockIdx.y; c < NCH; c += 32) {
        int prev = (c + NCH - 1) % NCH;
        if (lane < 8) {
            int slot = (lane < 4) ? (c * 4 + lane) : (prev * 4 + lane - 4);
            sfull[w][lane] = g_stick[sbase + slot];
        }
        __syncwarp();
        if (only_pos >= 0) {
            bool hit = (lane < 4) && (sfull[w][lane] % TP == only_pos);
            if (!__ballot_sync(0xffffffffu, hit)) continue;
        }
        for (int idx = lane; idx < 8 * DHD; idx += 32) {
            int r = idx >> 6, d = idx & 63;
            int pos = sfull[w][r] % TP;
            size_t g = (size_t)(b * TP + pos) * DM + head * DHD + d;
            sk[w][r * KST + d] = g_qk[g];
            sv[w][r * KST + d] = g_v[g];
        }
        __syncwarp();
        if (lane < 8) {
            float ss = 0.f;
#pragma unroll 16
            for (int d = 0; d < 64; ++d) { float vv = sk[w][lane * KST + d]; ss += vv * vv; }
            srn[w][lane] = 1.f / sqrtf(fmaxf(ss, 1e-24f));
        }
        __syncwarp();
        int i = lane >> 3, j = lane & 7;
        float s = 0.f;
#pragma unroll 16
        for (int d = 0; d < 64; ++d) s += sk[w][i * KST + d] * sk[w][j * KST + d];
        s *= srn[w][j] * 0.125f;
        int fi = sfull[w][i], fj = sfull[w][j];
        if ((fi % TP) == (fj % TP)) s = -5e4f;
        float m = s;
        m = fmaxf(m, __shfl_xor_sync(0xffffffffu, m, 1, 8));
        m = fmaxf(m, __shfl_xor_sync(0xffffffffu, m, 2, 8));
        m = fmaxf(m, __shfl_xor_sync(0xffffffffu, m, 4, 8));
        float e = expf(s - m);
        float sum = e;
        sum += __shfl_xor_sync(0xffffffffu, sum, 1, 8);
        sum += __shfl_xor_sync(0xffffffffu, sum, 2, 8);
        sum += __shfl_xor_sync(0xffffffffu, sum, 4, 8);
        float lse = m + logf(sum);
        float wgt = e / sum;
        float acc[8];
#pragma unroll
        for (int d = 0; d < 8; ++d) acc[d] = 0.f;
#pragma unroll
        for (int jj = 0; jj < 8; ++jj) {
            float wj = __shfl_sync(0xffffffffu, wgt, (i << 3) | jj);
#pragma unroll
            for (int d = 0; d < 8; ++d) acc[d] += wj * sv[w][jj * KST + j * 8 + d];
        }
        int h = fi / TP, pos = fi - h * TP;
        float* op = g_ohash + (size_t)((bh * NHASH + h) * TP + pos) * DHD + j * 8;
        *(float4*)op       = make_float4(acc[0], acc[1], acc[2], acc[3]);
        *(float4*)(op + 4) = make_float4(acc[4], acc[5], acc[6], acc[7]);
        if (j == 0) g_lse[(bh * NHASH + h) * TP + pos] = lse;
        __syncwarp();
    }
}

// ---------------- combine hash rounds (all 8 heads per block) ----------------
__global__ void combine_kernel(int tbase) {
    int t = tbase + blockIdx.x, b = blockIdx.y;
    int tid = threadIdx.x;
    int head = tid >> 6, d = tid & 63;
    int bh = b * 8 + head;
    int base = bh * (NHASH * TP) + t;
    float l0 = g_lse[base], l1 = g_lse[base + TP];
    float l2 = g_lse[base + 2 * TP], l3 = g_lse[base + 3 * TP];
    float m = fmaxf(fmaxf(l0, l1), fmaxf(l2, l3));
    float e0 = expf(l0 - m), e1 = expf(l1 - m), e2 = expf(l2 - m), e3 = expf(l3 - m);
    float inv = 1.f / (e0 + e1 + e2 + e3);
    size_t ob = (size_t)base * DHD + d;
    size_t st = (size_t)TP * DHD;
    float acc = e0 * g_ohash[ob] + e1 * g_ohash[ob + st]
              + e2 * g_ohash[ob + 2 * st] + e3 * g_ohash[ob + 3 * st];
    g_attn[(size_t)(b * TP + t) * DM + head * DHD + d] = acc * inv;
}

// ---------------- residual + LayerNorm (full rows) ----------------
__global__ void lnadd_kernel(const float* __restrict__ gam, const float* __restrict__ bet) {
    int r = blockIdx.x;
    int b = r / NTOK, n = r - b * NTOK;
    size_t off = (size_t)(b * TP + n) * DM;
    float* xr = g_x + off;
    const float* yr = g_y + off;
    int tid = threadIdx.x;
    float v0 = xr[tid] + yr[tid];
    float v1 = xr[tid + 256] + yr[tid + 256];
    __shared__ float red[256];
    red[tid] = v0 + v1;
    __syncthreads();
    for (int s = 128; s; s >>= 1) { if (tid < s) red[tid] += red[tid + s]; __syncthreads(); }
    float mean = red[0] * (1.f / 512.f);
    __syncthreads();
    float d0 = v0 - mean, d1 = v1 - mean;
    red[tid] = d0 * d0 + d1 * d1;
    __syncthreads();
    for (int s = 128; s; s >>= 1) { if (tid < s) red[tid] += red[tid + s]; __syncthreads(); }
    float rstd = 1.f / sqrtf(red[0] * (1.f / 512.f) + 1e-5f);
    xr[tid]       = d0 * rstd * gam[tid] + bet[tid];
    xr[tid + 256] = d1 * rstd * gam[tid + 256] + bet[tid + 256];
}

// ---------------- gather token-515 rows into compact buffers ----------------
__global__ void gather_kernel() {
    int idx = blockIdx.x * 256 + threadIdx.x;
    if (idx >= 128 * DM) return;
    int r = idx >> 9, d = idx & 511;
    float a = 0.f, x = 0.f;
    if (r < NBB) {
        size_t src = (size_t)(r * TP + (NTOK - 1)) * DM + d;
        a = g_attn[src];
        x = g_x[src];
    }
    g_cattn[idx] = a;
    g_cx[idx] = x;
}

// ---------------- compact residual + LayerNorm (32 rows) ----------------
__global__ void lnadd_c_kernel(const float* __restrict__ gam, const float* __restrict__ bet) {
    size_t off = (size_t)blockIdx.x * DM;
    float* xr = g_cx + off;
    const float* yr = g_cy + off;
    int tid = threadIdx.x;
    float v0 = xr[tid] + yr[tid];
    float v1 = xr[tid + 256] + yr[tid + 256];
    __shared__ float red[256];
    red[tid] = v0 + v1;
    __syncthreads();
    for (int s = 128; s; s >>= 1) { if (tid < s) red[tid] += red[tid + s]; __syncthreads(); }
    float mean = red[0] * (1.f / 512.f);
    __syncthreads();
    float d0 = v0 - mean, d1 = v1 - mean;
    red[tid] = d0 * d0 + d1 * d1;
    __syncthreads();
    for (int s = 128; s; s >>= 1) { if (tid < s) red[tid] += red[tid + s]; __syncthreads(); }
    float rstd = 1.f / sqrtf(red[0] * (1.f / 512.f) + 1e-5f);
    xr[tid]       = d0 * rstd * gam[tid] + bet[tid];
    xr[tid + 256] = d1 * rstd * gam[tid + 256] + bet[tid + 256];
}

// ---------------- final LN + projection (compact rows) ----------------
__global__ void final_kernel(const float* __restrict__ gF, const float* __restrict__ bF,
                             const float* __restrict__ Wp, const float* __restrict__ bp) {
    int b = blockIdx.x;
    int tid = threadIdx.x;
    const float* xr = g_cx + (size_t)b * DM;
    float v = xr[tid];
    __shared__ float red[512];
    red[tid] = v; __syncthreads();
    for (int s = 256; s; s >>= 1) { if (tid < s) red[tid] += red[tid + s]; __syncthreads(); }
    float mean = red[0] * (1.f / 512.f);
    __syncthreads();
    float d = v - mean;
    red[tid] = d * d; __syncthreads();
    for (int s = 256; s; s >>= 1) { if (tid < s) red[tid] += red[tid + s]; __syncthreads(); }
    float rstd = 1.f / sqrtf(red[0] * (1.f / 512.f) + 1e-5f);
    __syncthreads();
    float nv = d * rstd * gF[tid] + bF[tid];
    red[tid] = nv * Wp[tid]; __syncthreads();
    for (int s = 256; s; s >>= 1) { if (tid < s) red[tid] += red[tid + s]; __syncthreads(); }
    if (tid == 0) g_dec[b] = red[0] + bp[0];
}

// ---------------- broadcast output ----------------
__global__ void out_kernel(float* __restrict__ out) {
    int idx = blockIdx.x * 256 + threadIdx.x;
    if (idx >= NBB * NBB * EIN) return;
    int i = idx >> 14;
    int rem = idx & 16383;
    int j = rem >> 9;
    int e = rem & 511;
    out[idx] = g_dec[j] * g_std[i * EIN + e] + g_mean[i * EIN + e];
}

// ---------------- host orchestration ----------------
static float* s_wp;

static inline void gemm(const float* A, size_t woff, const float* bias,
                        float* C, float* C2, int M, int N, int K,
                        int ldc, int nsplit, int flags) {
    dim3 g(N / 128, M / 128), b(256);
    gemm_3xtf32<<<g, b, GEMM_SMEM>>>(A, s_wp + 2 * woff, bias, C, C2, K, N, ldc, nsplit, flags);
}

extern "C" void kernel_launch(void* const* d_in, const int* in_sizes, int n_in,
                              void* d_out, int out_size) {
    (void)in_sizes; (void)n_in; (void)out_size;
    const float* x_enc  = (const float*)d_in[0];
    const float* x_mark = (const float*)d_in[1];
    const float* W_emb  = (const float*)d_in[2];
    const float* b_emb  = (const float*)d_in[3];
    const float* Wqk    = (const float*)d_in[4];
    const float* Wv     = (const float*)d_in[5];
    const float* Wo     = (const float*)d_in[6];
    const float* bo     = (const float*)d_in[7];
    const float* Wc1    = (const float*)d_in[8];
    const float* bc1    = (const float*)d_in[9];
    const float* Wc2    = (const float*)d_in[10];
    const float* bc2    = (const float*)d_in[11];
    const float* g1     = (const float*)d_in[12];
    const float* b1     = (const float*)d_in[13];
    const float* g2     = (const float*)d_in[14];
    const float* b2     = (const float*)d_in[15];
    const float* gF     = (const float*)d_in[16];
    const float* bF     = (const float*)d_in[17];
    const float* Wp     = (const float*)d_in[18];
    const float* bp     = (const float*)d_in[19];
    const float* rot    = (const float*)d_in[20];

    cudaFuncSetAttribute(gemm_3xtf32, cudaFuncAttributeMaxDynamicSharedMemorySize, GEMM_SMEM);

    float *px, *pqk, *pv, *pattn, *py, *ph, *pca, *pcx, *pcy, *pch;
    cudaGetSymbolAddress((void**)&px,    g_x);
    cudaGetSymbolAddress((void**)&pqk,   g_qk);
    cudaGetSymbolAddress((void**)&pv,    g_v);
    cudaGetSymbolAddress((void**)&pattn, g_attn);
    cudaGetSymbolAddress((void**)&py,    g_y);
    cudaGetSymbolAddress((void**)&ph,    g_h);
    cudaGetSymbolAddress((void**)&pca,   g_cattn);
    cudaGetSymbolAddress((void**)&pcx,   g_cx);
    cudaGetSymbolAddress((void**)&pcy,   g_cy);
    cudaGetSymbolAddress((void**)&pch,   g_ch);
    cudaGetSymbolAddress((void**)&s_wp,  g_wp);

    // split all weights into interleaved (hi,lo) pair planes.
    // QKV concat per layer: Wqk rows 0..511, Wv rows 512..1023.
    const int WQ = DM * DM;         // 262144
    const int WC = DFF * DM;        // 1048576
#define SPLW(src, dstoff, n) splitw_kernel<<<((n)/2 + 255)/256, 256>>>((src), s_wp + 2*(size_t)(dstoff), (n)/2)
    SPLW(W_emb,            OFF_EMB,             WQ);
    SPLW(Wqk,              OFF_QKV0,            WQ);
    SPLW(Wv,               OFF_QKV0 + WQ,       WQ);
    SPLW(Wqk + WQ,         OFF_QKV1,            WQ);
    SPLW(Wv + WQ,          OFF_QKV1 + WQ,       WQ);
    SPLW(Wo,               OFF_O0,              WQ);
    SPLW(Wo + WQ,          OFF_O1,              WQ);
    SPLW(Wc1,              OFF_C1_0,            WC);
    SPLW(Wc1 + WC,         OFF_C1_1,            WC);
    SPLW(Wc2,              OFF_C2_0,            WC);
    SPLW(Wc2 + WC,         OFF_C2_1,            WC);
#undef SPLW

    tok_stats_kernel<<<dim3(EIN / 32, NBB), dim3(32, 8)>>>(x_enc);
    marks_kernel<<<(NBB * NMARK * LSEQ + 255) / 256, 256>>>(x_mark);
    zeropad_kernel<<<(NBB * 4 * DM + 255) / 256, 256>>>();

    const int BIG = 1 << 30;
    // embedding: tok [16512,512] @ W_emb^T -> g_x (row remap to 520 stride)
    gemm(pattn, OFF_EMB, b_emb, px, nullptr, MTOK, DM, LSEQ, DM, BIG, 2);

    // ---- layer 0: full ----
    gemm(px, OFF_QKV0, nullptr, pqk, pv, MROWS, 2 * DM, DM, DM, DM, 0);  // fused QK+V
    hash_kernel<<<dim3(NHASH, BHN), 256>>>(rot);
    sort_kernel<<<BHN, 256>>>();
    attn_kernel<<<dim3(BHN, 4), 256>>>(-1);
    combine_kernel<<<dim3(TP, NBB), 512>>>(0);
    gemm(pattn, OFF_O0, bo, py, nullptr, MROWS, DM, DM, DM, BIG, 0);
    lnadd_kernel<<<MTOK, 256>>>(g1, b1);
    gemm(px, OFF_C1_0, bc1, ph, nullptr, MROWS, DFF, DM, DFF, BIG, 1);
    gemm(ph, OFF_C2_0, bc2, py, nullptr, MROWS, DM, DFF, DM, BIG, 0);
    lnadd_kernel<<<MTOK, 256>>>(g2, b2);

    // ---- layer 1: attention full, post-attention pruned to token 515 ----
    gemm(px, OFF_QKV1, nullptr, pqk, pv, MROWS, 2 * DM, DM, DM, DM, 0);  // fused QK+V
    hash_kernel<<<dim3(NHASH, BHN), 256>>>(rot + (size_t)DHD * NHASH * 65);
    sort_kernel<<<BHN, 256>>>();
    attn_kernel<<<dim3(BHN, 4), 256>>>(NTOK - 1);
    combine_kernel<<<dim3(1, NBB), 512>>>(NTOK - 1);
    gather_kernel<<<(128 * DM + 255) / 256, 256>>>();
    gemm(pca, OFF_O1, bo + DM, pcy, nullptr, 128, DM, DM, DM, BIG, 0);
    lnadd_c_kernel<<<NBB, 256>>>(g1 + DM, b1 + DM);
    gemm(pcx, OFF_C1_1, bc1 + DFF, pch, nullptr, 128, DFF, DM, DFF, BIG, 1);
    gemm(pch, OFF_C2_1, bc2 + DM, pcy, nullptr, 128, DM, DFF, DM, BIG, 0);
    lnadd_c_kernel<<<NBB, 256>>>(g2 + DM, b2 + DM);

    final_kernel<<<NBB, 512>>>(gF, bF, Wp, bp);
    out_kernel<<<(NBB * NBB * EIN + 255) / 256, 256>>>((float*)d_out);
}

// round 16
// speedup vs baseline: 1.0726x; 1.0726x over previous
#include <cuda_runtime.h>
#include <math.h>
#include <stdint.h>

// ---------------- model constants ----------------
#define NBB 32
#define LSEQ 512
#define EIN 512
#define NMARK 4
#define DM 512
#define HH 8
#define DFF 2048
#define NL 2
#define NHASH 4
#define NTOK 516
#define TP 520
#define DHD 64
#define NB 130
#define NBINS 520
#define NCH 520
#define BHN 256
#define MROWS (NBB*TP)   // 16640
#define MTOK (NBB*NTOK)  // 16512
#define KST 68

// GEMM tiling: stage = [A 16KB | Bhi 16KB | Blo 16KB]  (R14 layout, known-good)
#define STAGES 2
#define CHUNK_BYTES 16384
#define STAGE_BYTES (3*CHUNK_BYTES)      // 49152
#define GEMM_SMEM (STAGES*STAGE_BYTES)   // 98304

// weight scratch offsets (floats)
#define OFF_EMB   0
#define OFF_QKV0  262144
#define OFF_QKV1  786432
#define OFF_O0    1310720
#define OFF_O1    1572864
#define OFF_C1_0  1835008
#define OFF_C1_1  2883584
#define OFF_C2_0  3932160
#define OFF_C2_1  4980736
#define GW_TOT    6029312

// ---------------- device scratch ----------------
__device__ float g_x[MROWS * DM];
__device__ float g_qk[MROWS * DM];
__device__ float g_v[MROWS * DM];
__device__ float g_attn[MROWS * DM];
__device__ float g_y[MROWS * DM];
__device__ float g_h[MROWS * DFF];
__device__ float g_whi[GW_TOT];
__device__ float g_wlo[GW_TOT];
__device__ float g_ohash[BHN * NHASH * TP * DHD];
__device__ float g_lse[BHN * NHASH * TP];
__device__ int   g_bin[BHN * NHASH * TP];
__device__ int   g_stick[BHN * NHASH * TP];
__device__ float g_mean[NBB * EIN];
__device__ float g_std[NBB * EIN];
__device__ float g_dec[NBB];
// compact layer-2 buffers (rows 0..31 real, 32..127 zero pad)
__device__ float g_cattn[128 * DM];
__device__ float g_cx[128 * DM];
__device__ float g_cy[128 * DM];
__device__ float g_ch[128 * DFF];

// ---------------- helpers ----------------
__device__ __forceinline__ uint32_t s2u(const void* p) {
    uint32_t a;
    asm("{ .reg .u64 t; cvta.to.shared.u64 t, %1; cvt.u32.u64 %0, t; }" : "=r"(a) : "l"(p));
    return a;
}
__device__ __forceinline__ uint32_t swz(uint32_t x) { return x ^ ((x >> 3) & 0x70); }
__device__ __forceinline__ uint32_t lds_u(uint32_t a) {
    uint32_t v;
    asm volatile("ld.shared.b32 %0, [%1];" : "=r"(v) : "r"(a));
    return v;
}
// split fp32 into tf32 hi + tf32 lo (x ~= hi + lo)
__device__ __forceinline__ void split_tf32(uint32_t xu, uint32_t& hi, uint32_t& lo) {
    float x = __uint_as_float(xu);
    uint32_t h;
    asm("cvt.rna.tf32.f32 %0, %1;" : "=r"(h) : "f"(x));
    float lf = x - __uint_as_float(h);
    uint32_t l;
    asm("cvt.rna.tf32.f32 %0, %1;" : "=r"(l) : "f"(lf));
    hi = h; lo = l;
}
__device__ __forceinline__ void cpwait(int n) {
    if (n <= 0) asm volatile("cp.async.wait_group 0;" ::: "memory");
    else        asm volatile("cp.async.wait_group 1;" ::: "memory");
}
// stage = [A | Bhi | Blo], each 128 rows x 32 f32, SW128
__device__ __forceinline__ void ld_chunk(const float* __restrict__ A,
                                         const float* __restrict__ Whi,
                                         const float* __restrict__ Wlo, int K,
                                         int bm, int bn, int c, uint32_t stg, int tid) {
#pragma unroll
    for (int pl = 0; pl < 3; ++pl) {
        const float* base = (pl == 0) ? A + (size_t)bm * K
                          : (pl == 1) ? Whi + (size_t)bn * K
                                      : Wlo + (size_t)bn * K;
        uint32_t pbase = stg + (uint32_t)pl * CHUNK_BYTES;
#pragma unroll
        for (int it = 0; it < 4; ++it) {
            int idx = it * 256 + tid;
            int r = idx >> 3, g = idx & 7;
            const float* src = base + (size_t)r * K + (c << 5) + (g << 2);
            uint32_t dst = pbase + swz((uint32_t)(r * 128 + g * 16));
            asm volatile("cp.async.cg.shared.global [%0], [%1], 16;" :: "r"(dst), "l"(src));
        }
    }
    asm volatile("cp.async.commit_group;" ::: "memory");
}

#define MMA_TF32(cc, a0, a1, a2, a3, b0, b1) \
    asm("mma.sync.aligned.m16n8k8.row.col.f32.tf32.tf32.f32 " \
        "{%0,%1,%2,%3}, {%4,%5,%6,%7}, {%8,%9}, {%0,%1,%2,%3};" \
        : "+f"((cc)[0]), "+f"((cc)[1]), "+f"((cc)[2]), "+f"((cc)[3]) \
        : "r"(a0), "r"(a1), "r"(a2), "r"(a3), "r"(b0), "r"(b1))

// ---------------- split-tf32 (3xTF32) tensor-core GEMM ----------------
// C[M,N] = A[M,K] * W[N,K]^T (+bias)(+relu); W as precomputed hi/lo planes.
// M,N mult of 128, K mult of 32. flags: 1 = relu, 2 = row remap 516->520.
// Columns >= nsplit are routed to C2 (at col-nsplit); both outputs use leading dim ldc.
__global__ void __launch_bounds__(256) gemm_3xtf32(
    const float* __restrict__ A, const float* __restrict__ Whi,
    const float* __restrict__ Wlo,
    const float* __restrict__ bias, float* __restrict__ C, float* __restrict__ C2,
    int K, int ldc, int nsplit, int flags)
{
    extern __shared__ char smem[];
    uint32_t sb = s2u(smem);
    int tid = threadIdx.x, wid = tid >> 5, lane = tid & 31;
    int gid = lane >> 2, tig = lane & 3;
    int warp_m = wid & 3, warp_n = wid >> 2;        // 4 x 2 warp layout
    int bm = blockIdx.y * 128, bn = blockIdx.x * 128;
    const int NC = K >> 5;
    const uint32_t gmask = (uint32_t)gid << 4;

    float acc[2][8][4];
#pragma unroll
    for (int m = 0; m < 2; ++m)
#pragma unroll
        for (int n = 0; n < 8; ++n)
#pragma unroll
            for (int q = 0; q < 4; ++q) acc[m][n][q] = 0.f;

#pragma unroll
    for (int p = 0; p < STAGES; ++p)
        ld_chunk(A, Whi, Wlo, K, bm, bn, p, sb + p * STAGE_BYTES, tid);

    for (int c = 0; c < NC; ++c) {
        int s = c & 1;
        int pend = NC - 1 - c; if (pend > STAGES - 1) pend = STAGES - 1;
        cpwait(pend);
        __syncthreads();
        uint32_t aA  = sb + s * STAGE_BYTES;
        uint32_t aBh = aA + CHUNK_BYTES;
        uint32_t aBl = aA + 2 * CHUNK_BYTES;
#pragma unroll
        for (int kq = 0; kq < 4; ++kq) {
            uint32_t k4 = (uint32_t)kq * 32;
            uint32_t kx0 = (k4 ^ gmask) + (uint32_t)tig * 4;
            uint32_t kx1 = ((k4 + 16) ^ gmask) + (uint32_t)tig * 4;
            uint32_t ah[2][4], al[2][4];
#pragma unroll
            for (int m = 0; m < 2; ++m) {
                uint32_t r0 = aA + (uint32_t)(warp_m * 32 + m * 16 + gid) * 128;
                uint32_t r1 = r0 + 8 * 128;
                split_tf32(lds_u(r0 + kx0), ah[m][0], al[m][0]);
                split_tf32(lds_u(r1 + kx0), ah[m][1], al[m][1]);
                split_tf32(lds_u(r0 + kx1), ah[m][2], al[m][2]);
                split_tf32(lds_u(r1 + kx1), ah[m][3], al[m][3]);
            }
#pragma unroll
            for (int n = 0; n < 8; ++n) {
                uint32_t roff = (uint32_t)(warp_n * 64 + n * 8 + gid) * 128;
                uint32_t bh0 = lds_u(aBh + roff + kx0);
                uint32_t bh1 = lds_u(aBh + roff + kx1);
                uint32_t bl0 = lds_u(aBl + roff + kx0);
                uint32_t bl1 = lds_u(aBl + roff + kx1);
#pragma unroll
                for (int m = 0; m < 2; ++m) {
                    MMA_TF32(acc[m][n], al[m][0], al[m][1], al[m][2], al[m][3], bh0, bh1);
                    MMA_TF32(acc[m][n], ah[m][0], ah[m][1], ah[m][2], ah[m][3], bl0, bl1);
                    MMA_TF32(acc[m][n], ah[m][0], ah[m][1], ah[m][2], ah[m][3], bh0, bh1);
                }
            }
        }
        __syncthreads();
        if (c + STAGES < NC)
            ld_chunk(A, Whi, Wlo, K, bm, bn, c + STAGES, sb + s * STAGE_BYTES, tid);
    }

    // epilogue (column routing for fused outputs)
    float* Ct = C;
    int cb = bn;
    if (bn >= nsplit) { Ct = C2; cb = bn - nsplit; }
#pragma unroll
    for (int m = 0; m < 2; ++m) {
        int r0 = bm + warp_m * 32 + m * 16 + gid;
        int r1 = r0 + 8;
        int o0 = r0, o1 = r1;
        if (flags & 2) {
            int bb0 = r0 / 516; o0 = bb0 * 520 + (r0 - bb0 * 516);
            int bb1 = r1 / 516; o1 = bb1 * 520 + (r1 - bb1 * 516);
        }
#pragma unroll
        for (int n = 0; n < 8; ++n) {
            int cn0 = bn + warp_n * 64 + n * 8 + tig * 2;   // original col (bias index)
            int cnl = cb + warp_n * 64 + n * 8 + tig * 2;   // routed col
            float bx = 0.f, by = 0.f;
            if (bias) { float2 bv = *(const float2*)(bias + cn0); bx = bv.x; by = bv.y; }
            float v0 = acc[m][n][0] + bx, v1 = acc[m][n][1] + by;
            float v2 = acc[m][n][2] + bx, v3 = acc[m][n][3] + by;
            if (flags & 1) {
                v0 = fmaxf(v0, 0.f); v1 = fmaxf(v1, 0.f);
                v2 = fmaxf(v2, 0.f); v3 = fmaxf(v3, 0.f);
            }
            *(float2*)(Ct + (size_t)o0 * ldc + cnl) = make_float2(v0, v1);
            *(float2*)(Ct + (size_t)o1 * ldc + cnl) = make_float2(v2, v3);
        }
    }
}

// ---------------- weight splitting (elementwise, once) ----------------
__global__ void splitw_kernel(const float* __restrict__ s,
                              float* __restrict__ hi, float* __restrict__ lo, int n4) {
    int i = blockIdx.x * 256 + threadIdx.x;
    if (i >= n4) return;
    float4 v = ((const float4*)s)[i];
    float4 h4, l4;
    uint32_t h, l;
    split_tf32(__float_as_uint(v.x), h, l); h4.x = __uint_as_float(h); l4.x = __uint_as_float(l);
    split_tf32(__float_as_uint(v.y), h, l); h4.y = __uint_as_float(h); l4.y = __uint_as_float(l);
    split_tf32(__float_as_uint(v.z), h, l); h4.z = __uint_as_float(h); l4.z = __uint_as_float(l);
    split_tf32(__float_as_uint(v.w), h, l); h4.w = __uint_as_float(h); l4.w = __uint_as_float(l);
    ((float4*)hi)[i] = h4;
    ((float4*)lo)[i] = l4;
}

// ---------------- RevIN + tokenization ----------------
__global__ void tok_stats_kernel(const float* __restrict__ xe) {
    int b = blockIdx.y;
    int tx = threadIdx.x, ty = threadIdx.y;
    int e = blockIdx.x * 32 + tx;
    const float* p = xe + (size_t)b * LSEQ * EIN + e;
    float s = 0.f, s2 = 0.f;
    for (int l = ty; l < LSEQ; l += 8) {
        float v = p[(size_t)l * EIN];
        s += v; s2 += v * v;
    }
    __shared__ float sh[8][32], sh2[8][32], shm[32], shr[32];
    sh[ty][tx] = s; sh2[ty][tx] = s2;
    __syncthreads();
    if (ty == 0) {
        float ts = 0.f, ts2 = 0.f;
        for (int r = 0; r < 8; ++r) { ts += sh[r][tx]; ts2 += sh2[r][tx]; }
        float m = ts * (1.f / 512.f);
        float var = ts2 * (1.f / 512.f) - m * m;
        if (var < 0.f) var = 0.f;
        float sd = sqrtf(var + 1e-5f);
        g_mean[b * EIN + e] = m;
        g_std[b * EIN + e] = sd;
        shm[tx] = m; shr[tx] = 1.f / sd;
    }
    __syncthreads();
    float m = shm[tx], r = shr[tx];
    float* orow = g_attn + (size_t)(b * NTOK + e) * LSEQ;
    for (int l = ty; l < LSEQ; l += 8)
        orow[l] = (p[(size_t)l * EIN] - m) * r;
}

__global__ void marks_kernel(const float* __restrict__ xm) {
    int idx = blockIdx.x * 256 + threadIdx.x;
    if (idx >= NBB * NMARK * LSEQ) return;
    int b = idx / (NMARK * LSEQ);
    int rem = idx - b * NMARK * LSEQ;
    int j = rem / LSEQ, l = rem - j * LSEQ;
    g_attn[(size_t)(b * NTOK + EIN + j) * LSEQ + l] =
        xm[((size_t)b * LSEQ + l) * NMARK + j];
}

__global__ void zeropad_kernel() {
    int idx = blockIdx.x * 256 + threadIdx.x;
    if (idx >= NBB * 4 * DM) return;
    int b = idx / (4 * DM);
    int rem = idx - b * 4 * DM;
    int j = rem / DM, d = rem - j * DM;
    g_x[(size_t)(b * TP + NTOK + j) * DM + d] = 0.f;
}

// ---------------- LSH hashing (8 t per warp, register-blocked) ----------------
__global__ void hash_kernel(const float* __restrict__ rotl) {
    int h = blockIdx.x;
    int bh = blockIdx.y;
    int b = bh >> 3, head = bh & 7;
    __shared__ float rs[65 * 64];          // rs[f*65 + i]
    __shared__ float sq[8][8][64];         // [warp][j][f]
    int tid = threadIdx.x;
    for (int idx = tid; idx < 65 * 64; idx += 256) {
        int f = idx / 65, i = idx - f * 65;
        rs[idx] = rotl[(size_t)f * (NHASH * 65) + h * 65 + i];
    }
    __syncthreads();
    int w = tid >> 5, lane = tid & 31;
    for (int t8 = w; t8 < 65; t8 += 8) {
        int t0 = t8 * 8;
        for (int idx = lane; idx < 128; idx += 32) {
            int j = idx >> 4, f4 = idx & 15;
            const float4* qrow = (const float4*)(g_qk + (size_t)(b * TP + t0 + j) * DM + head * DHD);
            *(float4*)&sq[w][j][f4 * 4] = qrow[f4];
        }
        __syncwarp();
        float a0[8], a1[8], a2[8];
#pragma unroll
        for (int j = 0; j < 8; ++j) { a0[j] = 0.f; a1[j] = 0.f; a2[j] = 0.f; }
#pragma unroll 4
        for (int f4 = 0; f4 < 16; ++f4) {
            float4 q[8];
#pragma unroll
            for (int j = 0; j < 8; ++j) q[j] = *(const float4*)&sq[w][j][f4 * 4];
#pragma unroll
            for (int ff = 0; ff < 4; ++ff) {
                int f = f4 * 4 + ff;
                float r0 = rs[f * 65 + lane];
                float r1 = rs[f * 65 + lane + 32];
                float r2 = rs[f * 65 + 64];
#pragma unroll
                for (int j = 0; j < 8; ++j) {
                    float qv = (ff == 0) ? q[j].x : (ff == 1) ? q[j].y : (ff == 2) ? q[j].z : q[j].w;
                    a0[j] += qv * r0;
                    a1[j] += qv * r1;
                    a2[j] += qv * r2;
                }
            }
        }
#pragma unroll
        for (int j = 0; j < 8; ++j) {
            float best = a0[j]; int bidx = lane;
            float n0 = -a0[j];
            if (n0 > best || (n0 == best && lane + 65 < bidx)) { best = n0; bidx = lane + 65; }
            float d1 = a1[j]; int i1 = lane + 32;
            if (d1 > best || (d1 == best && i1 < bidx)) { best = d1; bidx = i1; }
            float n1 = -d1;
            if (n1 > best || (n1 == best && i1 + 65 < bidx)) { best = n1; bidx = i1 + 65; }
            if (lane == 0) {
                float d2 = a2[j];
                if (d2 > best || (d2 == best && 64 < bidx)) { best = d2; bidx = 64; }
                float n2 = -d2;
                if (n2 > best || (n2 == best && 129 < bidx)) { best = n2; bidx = 129; }
            }
            for (int off = 16; off; off >>= 1) {
                float ov = __shfl_xor_sync(0xffffffffu, best, off);
                int oi  = __shfl_xor_sync(0xffffffffu, bidx, off);
                if (ov > best || (ov == best && oi < bidx)) { best = ov; bidx = oi; }
            }
            if (lane == 0) g_bin[(bh * NHASH + h) * TP + t0 + j] = bidx + h * NB;
        }
        __syncwarp();
    }
}

// ---------------- stable counting sort ----------------
__global__ void sort_kernel() {
    int bh = blockIdx.x;
    int tid = threadIdx.x;
    __shared__ int cnt[NBINS], off[NBINS];
    for (int i = tid; i < NBINS; i += 256) cnt[i] = 0;
    __syncthreads();
    for (int i = tid; i < NHASH * TP; i += 256)
        atomicAdd(&cnt[g_bin[bh * (NHASH * TP) + i]], 1);
    __syncthreads();
    if (tid < 32) {
        int carry = 0;
        for (int c = 0; c < NBINS; c += 32) {
            int idx = c + tid;
            int v = (idx < NBINS) ? cnt[idx] : 0;
            int own = v;
            for (int d = 1; d < 32; d <<= 1) {
                int t2 = __shfl_up_sync(0xffffffffu, v, d);
                if (tid >= d) v += t2;
            }
            if (idx < NBINS) off[idx] = (v - own) + carry;
            carry += __shfl_sync(0xffffffffu, v, 31);
        }
    }
    __syncthreads();
    int w = tid >> 5, lane = tid & 31;
    if (w < NHASH) {
        for (int base = 0; base < TP; base += 32) {
            int pos = base + lane;
            bool act = pos < TP;
            unsigned mask = __ballot_sync(0xffffffffu, act);
            if (act) {
                int bin = g_bin[bh * (NHASH * TP) + w * TP + pos];
                unsigned peers = __match_any_sync(mask, bin);
                int leader = __ffs(peers) - 1;
                int rank = __popc(peers & ((1u << lane) - 1));
                int baseoff = 0;
                if (lane == leader) baseoff = atomicAdd(&off[bin], __popc(peers));
                baseoff = __shfl_sync(peers, baseoff, leader);
                g_stick[bh * (NHASH * TP) + baseoff + rank] = w * TP + pos;
            }
            __syncwarp();
        }
    }
}

// ---------------- chunked LSH attention ----------------
__global__ void attn_kernel(int only_pos) {
    int bh = blockIdx.x;
    int b = bh >> 3, head = bh & 7;
    int tid = threadIdx.x, w = tid >> 5, lane = tid & 31;
    __shared__ float sk[8][8 * KST];
    __shared__ float sv[8][8 * KST];
    __shared__ int   sfull[8][8];
    __shared__ float srn[8][8];
    const int sbase = bh * (NHASH * TP);

    for (int c = w + 8 * blockIdx.y; c < NCH; c += 32) {
        int prev = (c + NCH - 1) % NCH;
        if (lane < 8) {
            int slot = (lane < 4) ? (c * 4 + lane) : (prev * 4 + lane - 4);
            sfull[w][lane] = g_stick[sbase + slot];
        }
        __syncwarp();
        if (only_pos >= 0) {
            bool hit = (lane < 4) && (sfull[w][lane] % TP == only_pos);
            if (!__ballot_sync(0xffffffffu, hit)) continue;
        }
        for (int idx = lane; idx < 8 * DHD; idx += 32) {
            int r = idx >> 6, d = idx & 63;
            int pos = sfull[w][r] % TP;
            size_t g = (size_t)(b * TP + pos) * DM + head * DHD + d;
            sk[w][r * KST + d] = g_qk[g];
            sv[w][r * KST + d] = g_v[g];
        }
        __syncwarp();
        if (lane < 8) {
            float ss = 0.f;
#pragma unroll 16
            for (int d = 0; d < 64; ++d) { float vv = sk[w][lane * KST + d]; ss += vv * vv; }
            srn[w][lane] = 1.f / sqrtf(fmaxf(ss, 1e-24f));
        }
        __syncwarp();
        int i = lane >> 3, j = lane & 7;
        float s = 0.f;
#pragma unroll 16
        for (int d = 0; d < 64; ++d) s += sk[w][i * KST + d] * sk[w][j * KST + d];
        s *= srn[w][j] * 0.125f;
        int fi = sfull[w][i], fj = sfull[w][j];
        if ((fi % TP) == (fj % TP)) s = -5e4f;
        float m = s;
        m = fmaxf(m, __shfl_xor_sync(0xffffffffu, m, 1, 8));
        m = fmaxf(m, __shfl_xor_sync(0xffffffffu, m, 2, 8));
        m = fmaxf(m, __shfl_xor_sync(0xffffffffu, m, 4, 8));
        float e = expf(s - m);
        float sum = e;
        sum += __shfl_xor_sync(0xffffffffu, sum, 1, 8);
        sum += __shfl_xor_sync(0xffffffffu, sum, 2, 8);
        sum += __shfl_xor_sync(0xffffffffu, sum, 4, 8);
        float lse = m + logf(sum);
        float wgt = e / sum;
        float acc[8];
#pragma unroll
        for (int d = 0; d < 8; ++d) acc[d] = 0.f;
#pragma unroll
        for (int jj = 0; jj < 8; ++jj) {
            float wj = __shfl_sync(0xffffffffu, wgt, (i << 3) | jj);
#pragma unroll
            for (int d = 0; d < 8; ++d) acc[d] += wj * sv[w][jj * KST + j * 8 + d];
        }
        int h = fi / TP, pos = fi - h * TP;
        float* op = g_ohash + (size_t)((bh * NHASH + h) * TP + pos) * DHD + j * 8;
        *(float4*)op       = make_float4(acc[0], acc[1], acc[2], acc[3]);
        *(float4*)(op + 4) = make_float4(acc[4], acc[5], acc[6], acc[7]);
        if (j == 0) g_lse[(bh * NHASH + h) * TP + pos] = lse;
        __syncwarp();
    }
}

// ---------------- combine hash rounds (8 heads per block) ----------------
__global__ void combine_kernel(int tbase) {
    int t = tbase + blockIdx.x, b = blockIdx.y;
    int tid = threadIdx.x;
    int head = tid >> 6, d = tid & 63;
    int bh = b * 8 + head;
    int base = bh * (NHASH * TP) + t;
    float l0 = g_lse[base], l1 = g_lse[base + TP];
    float l2 = g_lse[base + 2 * TP], l3 = g_lse[base + 3 * TP];
    float m = fmaxf(fmaxf(l0, l1), fmaxf(l2, l3));
    float e0 = expf(l0 - m), e1 = expf(l1 - m), e2 = expf(l2 - m), e3 = expf(l3 - m);
    float inv = 1.f / (e0 + e1 + e2 + e3);
    size_t ob = (size_t)base * DHD + d;
    size_t st = (size_t)TP * DHD;
    float acc = e0 * g_ohash[ob] + e1 * g_ohash[ob + st]
              + e2 * g_ohash[ob + 2 * st] + e3 * g_ohash[ob + 3 * st];
    g_attn[(size_t)(b * TP + t) * DM + head * DHD + d] = acc * inv;
}

// ---------------- residual + LayerNorm (full rows) ----------------
__global__ void lnadd_kernel(const float* __restrict__ gam, const float* __restrict__ bet) {
    int r = blockIdx.x;
    int b = r / NTOK, n = r - b * NTOK;
    size_t off = (size_t)(b * TP + n) * DM;
    float* xr = g_x + off;
    const float* yr = g_y + off;
    int tid = threadIdx.x;
    float v0 = xr[tid] + yr[tid];
    float v1 = xr[tid + 256] + yr[tid + 256];
    __shared__ float red[256];
    red[tid] = v0 + v1;
    __syncthreads();
    for (int s = 128; s; s >>= 1) { if (tid < s) red[tid] += red[tid + s]; __syncthreads(); }
    float mean = red[0] * (1.f / 512.f);
    __syncthreads();
    float d0 = v0 - mean, d1 = v1 - mean;
    red[tid] = d0 * d0 + d1 * d1;
    __syncthreads();
    for (int s = 128; s; s >>= 1) { if (tid < s) red[tid] += red[tid + s]; __syncthreads(); }
    float rstd = 1.f / sqrtf(red[0] * (1.f / 512.f) + 1e-5f);
    xr[tid]       = d0 * rstd * gam[tid] + bet[tid];
    xr[tid + 256] = d1 * rstd * gam[tid + 256] + bet[tid + 256];
}

// ---------------- gather token-515 rows into compact buffers ----------------
__global__ void gather_kernel() {
    int idx = blockIdx.x * 256 + threadIdx.x;
    if (idx >= 128 * DM) return;
    int r = idx >> 9, d = idx & 511;
    float a = 0.f, x = 0.f;
    if (r < NBB) {
        size_t src = (size_t)(r * TP + (NTOK - 1)) * DM + d;
        a = g_attn[src];
        x = g_x[src];
    }
    g_cattn[idx] = a;
    g_cx[idx] = x;
}

// ---------------- compact residual + LayerNorm (32 rows) ----------------
__global__ void lnadd_c_kernel(const float* __restrict__ gam, const float* __restrict__ bet) {
    size_t off = (size_t)blockIdx.x * DM;
    float* xr = g_cx + off;
    const float* yr = g_cy + off;
    int tid = threadIdx.x;
    float v0 = xr[tid] + yr[tid];
    float v1 = xr[tid + 256] + yr[tid + 256];
    __shared__ float red[256];
    red[tid] = v0 + v1;
    __syncthreads();
    for (int s = 128; s; s >>= 1) { if (tid < s) red[tid] += red[tid + s]; __syncthreads(); }
    float mean = red[0] * (1.f / 512.f);
    __syncthreads();
    float d0 = v0 - mean, d1 = v1 - mean;
    red[tid] = d0 * d0 + d1 * d1;
    __syncthreads();
    for (int s = 128; s; s >>= 1) { if (tid < s) red[tid] += red[tid + s]; __syncthreads(); }
    float rstd = 1.f / sqrtf(red[0] * (1.f / 512.f) + 1e-5f);
    xr[tid]       = d0 * rstd * gam[tid] + bet[tid];
    xr[tid + 256] = d1 * rstd * gam[tid + 256] + bet[tid + 256];
}

// ---------------- final LN + projection (compact rows) ----------------
__global__ void final_kernel(const float* __restrict__ gF, const float* __restrict__ bF,
                             const float* __restrict__ Wp, const float* __restrict__ bp) {
    int b = blockIdx.x;
    int tid = threadIdx.x;
    const float* xr = g_cx + (size_t)b * DM;
    float v = xr[tid];
    __shared__ float red[512];
    red[tid] = v; __syncthreads();
    for (int s = 256; s; s >>= 1) { if (tid < s) red[tid] += red[tid + s]; __syncthreads(); }
    float mean = red[0] * (1.f / 512.f);
    __syncthreads();
    float d = v - mean;
    red[tid] = d * d; __syncthreads();
    for (int s = 256; s; s >>= 1) { if (tid < s) red[tid] += red[tid + s]; __syncthreads(); }
    float rstd = 1.f / sqrtf(red[0] * (1.f / 512.f) + 1e-5f);
    __syncthreads();
    float nv = d * rstd * gF[tid] + bF[tid];
    red[tid] = nv * Wp[tid]; __syncthreads();
    for (int s = 256; s; s >>= 1) { if (tid < s) red[tid] += red[tid + s]; __syncthreads(); }
    if (tid == 0) g_dec[b] = red[0] + bp[0];
}

// ---------------- broadcast output ----------------
__global__ void out_kernel(float* __restrict__ out) {
    int idx = blockIdx.x * 256 + threadIdx.x;
    if (idx >= NBB * NBB * EIN) return;
    int i = idx >> 14;
    int rem = idx & 16383;
    int j = rem >> 9;
    int e = rem & 511;
    out[idx] = g_dec[j] * g_std[i * EIN + e] + g_mean[i * EIN + e];
}

// ---------------- host orchestration ----------------
static float* s_whi; static float* s_wlo;

static inline void gemm(const float* A, size_t woff, const float* bias,
                        float* C, float* C2, int M, int N, int K,
                        int ldc, int nsplit, int flags) {
    dim3 g(N / 128, M / 128), b(256);
    gemm_3xtf32<<<g, b, GEMM_SMEM>>>(A, s_whi + woff, s_wlo + woff, bias, C, C2,
                                     K, ldc, nsplit, flags);
}

extern "C" void kernel_launch(void* const* d_in, const int* in_sizes, int n_in,
                              void* d_out, int out_size) {
    (void)in_sizes; (void)n_in; (void)out_size;
    const float* x_enc  = (const float*)d_in[0];
    const float* x_mark = (const float*)d_in[1];
    const float* W_emb  = (const float*)d_in[2];
    const float* b_emb  = (const float*)d_in[3];
    const float* Wqk    = (const float*)d_in[4];
    const float* Wv     = (const float*)d_in[5];
    const float* Wo     = (const float*)d_in[6];
    const float* bo     = (const float*)d_in[7];
    const float* Wc1    = (const float*)d_in[8];
    const float* bc1    = (const float*)d_in[9];
    const float* Wc2    = (const float*)d_in[10];
    const float* bc2    = (const float*)d_in[11];
    const float* g1     = (const float*)d_in[12];
    const float* b1     = (const float*)d_in[13];
    const float* g2     = (const float*)d_in[14];
    const float* b2     = (const float*)d_in[15];
    const float* gF     = (const float*)d_in[16];
    const float* bF     = (const float*)d_in[17];
    const float* Wp     = (const float*)d_in[18];
    const float* bp     = (const float*)d_in[19];
    const float* rot    = (const float*)d_in[20];

    cudaFuncSetAttribute(gemm_3xtf32, cudaFuncAttributeMaxDynamicSharedMemorySize, GEMM_SMEM);

    float *px, *pqk, *pv, *pattn, *py, *ph, *pca, *pcx, *pcy, *pch;
    cudaGetSymbolAddress((void**)&px,    g_x);
    cudaGetSymbolAddress((void**)&pqk,   g_qk);
    cudaGetSymbolAddress((void**)&pv,    g_v);
    cudaGetSymbolAddress((void**)&pattn, g_attn);
    cudaGetSymbolAddress((void**)&py,    g_y);
    cudaGetSymbolAddress((void**)&ph,    g_h);
    cudaGetSymbolAddress((void**)&pca,   g_cattn);
    cudaGetSymbolAddress((void**)&pcx,   g_cx);
    cudaGetSymbolAddress((void**)&pcy,   g_cy);
    cudaGetSymbolAddress((void**)&pch,   g_ch);
    cudaGetSymbolAddress((void**)&s_whi, g_whi);
    cudaGetSymbolAddress((void**)&s_wlo, g_wlo);

    // split all weights into hi/lo planes; per-layer QKV rows concatenated
    const int WQ = DM * DM;         // 262144
    const int WC = DFF * DM;        // 1048576
#define SPLW(src, dstoff, n) \
    splitw_kernel<<<((n)/4 + 255)/256, 256>>>((src), s_whi + (dstoff), s_wlo + (dstoff), (n)/4)
    SPLW(W_emb,    OFF_EMB,        WQ);
    SPLW(Wqk,      OFF_QKV0,       WQ);
    SPLW(Wv,       OFF_QKV0 + WQ,  WQ);
    SPLW(Wqk + WQ, OFF_QKV1,       WQ);
    SPLW(Wv + WQ,  OFF_QKV1 + WQ,  WQ);
    SPLW(Wo,       OFF_O0,         WQ);
    SPLW(Wo + WQ,  OFF_O1,         WQ);
    SPLW(Wc1,      OFF_C1_0,       WC);
    SPLW(Wc1 + WC, OFF_C1_1,       WC);
    SPLW(Wc2,      OFF_C2_0,       WC);
    SPLW(Wc2 + WC, OFF_C2_1,       WC);
#undef SPLW

    tok_stats_kernel<<<dim3(EIN / 32, NBB), dim3(32, 8)>>>(x_enc);
    marks_kernel<<<(NBB * NMARK * LSEQ + 255) / 256, 256>>>(x_mark);
    zeropad_kernel<<<(NBB * 4 * DM + 255) / 256, 256>>>();

    const int BIG = 1 << 30;
    // embedding: tok [16512,512] @ W_emb^T -> g_x (row remap to 520 stride)
    gemm(pattn, OFF_EMB, b_emb, px, nullptr, MTOK, DM, LSEQ, DM, BIG, 2);

    // ---- layer 0: full ----
    gemm(px, OFF_QKV0, nullptr, pqk, pv, MROWS, 2 * DM, DM, DM, DM, 0);  // fused QK+V
    hash_kernel<<<dim3(NHASH, BHN), 256>>>(rot);
    sort_kernel<<<BHN, 256>>>();
    attn_kernel<<<dim3(BHN, 4), 256>>>(-1);
    combine_kernel<<<dim3(TP, NBB), 512>>>(0);
    gemm(pattn, OFF_O0, bo, py, nullptr, MROWS, DM, DM, DM, BIG, 0);
    lnadd_kernel<<<MTOK, 256>>>(g1, b1);
    gemm(px, OFF_C1_0, bc1, ph, nullptr, MROWS, DFF, DM, DFF, BIG, 1);
    gemm(ph, OFF_C2_0, bc2, py, nullptr, MROWS, DM, DFF, DM, BIG, 0);
    lnadd_kernel<<<MTOK, 256>>>(g2, b2);

    // ---- layer 1: attention full, post-attention pruned to token 515 ----
    gemm(px, OFF_QKV1, nullptr, pqk, pv, MROWS, 2 * DM, DM, DM, DM, 0);  // fused QK+V
    hash_kernel<<<dim3(NHASH, BHN), 256>>>(rot + (size_t)DHD * NHASH * 65);
    sort_kernel<<<BHN, 256>>>();
    attn_kernel<<<dim3(BHN, 4), 256>>>(NTOK - 1);
    combine_kernel<<<dim3(1, NBB), 512>>>(NTOK - 1);
    gather_kernel<<<(128 * DM + 255) / 256, 256>>>();
    gemm(pca, OFF_O1, bo + DM, pcy, nullptr, 128, DM, DM, DM, BIG, 0);
    lnadd_c_kernel<<<NBB, 256>>>(g1 + DM, b1 + DM);
    gemm(pcx, OFF_C1_1, bc1 + DFF, pch, nullptr, 128, DFF, DM, DFF, BIG, 1);
    gemm(pch, OFF_C2_1, bc2 + DM, pcy, nullptr, 128, DM, DFF, DM, BIG, 0);
    lnadd_c_kernel<<<NBB, 256>>>(g2 + DM, b2 + DM);

    final_kernel<<<NBB, 512>>>(gF, bF, Wp, bp);
    out_kernel<<<(NBB * NBB * EIN + 255) / 256, 256>>>((float*)d_out);
}

// round 17
// speedup vs baseline: 1.1117x; 1.0364x over previous
#include <cuda_runtime.h>
#include <math.h>
#include <stdint.h>

// ---------------- model constants ----------------
#define NBB 32
#define LSEQ 512
#define EIN 512
#define NMARK 4
#define DM 512
#define HH 8
#define DFF 2048
#define NL 2
#define NHASH 4
#define NTOK 516
#define TP 520
#define DHD 64
#define NB 130
#define NBINS 520
#define NCH 520
#define BHN 256
#define MROWS (NBB*TP)   // 16640
#define MTOK (NBB*NTOK)  // 16512
#define KST 68

// GEMM tiling: stage = [A 16KB | Bhi 16KB | Blo 16KB]
#define STAGES 2
#define CHUNK_BYTES 16384
#define STAGE_BYTES (3*CHUNK_BYTES)      // 49152
#define GEMM_SMEM (STAGES*STAGE_BYTES)   // 98304

// weight scratch offsets (floats)
#define OFF_EMB   0
#define OFF_QKV0  262144
#define OFF_QKV1  786432
#define OFF_O0    1310720
#define OFF_O1    1572864
#define OFF_C1_0  1835008
#define OFF_C1_1  2883584
#define OFF_C2_0  3932160
#define OFF_C2_1  4980736
#define GW_TOT    6029312

// ---------------- device scratch ----------------
__device__ float g_x[MROWS * DM];
__device__ float g_qk[MROWS * DM];
__device__ float g_v[MROWS * DM];
__device__ float g_attn[MROWS * DM];
__device__ float g_y[MROWS * DM];
__device__ float g_h[MROWS * DFF];
__device__ float g_whi[GW_TOT];
__device__ float g_wlo[GW_TOT];
__device__ float g_ohash[BHN * NHASH * TP * DHD];
__device__ float g_lse[BHN * NHASH * TP];
__device__ int   g_bin[BHN * NHASH * TP];
__device__ int   g_stick[BHN * NHASH * TP];
__device__ float g_mean[NBB * EIN];
__device__ float g_std[NBB * EIN];
__device__ float g_dec[NBB];
// compact layer-2 buffers (rows 0..31 real, 32..127 zero pad)
__device__ float g_cattn[128 * DM];
__device__ float g_cx[128 * DM];
__device__ float g_cy[128 * DM];
__device__ float g_ch[128 * DFF];

// ---------------- helpers ----------------
__device__ __forceinline__ uint32_t s2u(const void* p) {
    uint32_t a;
    asm("{ .reg .u64 t; cvta.to.shared.u64 t, %1; cvt.u32.u64 %0, t; }" : "=r"(a) : "l"(p));
    return a;
}
__device__ __forceinline__ uint32_t swz(uint32_t x) { return x ^ ((x >> 3) & 0x70); }
__device__ __forceinline__ uint32_t lds_u(uint32_t a) {
    uint32_t v;
    asm volatile("ld.shared.b32 %0, [%1];" : "=r"(v) : "r"(a));
    return v;
}
// split fp32 into tf32 hi + tf32 lo (x ~= hi + lo)
__device__ __forceinline__ void split_tf32(uint32_t xu, uint32_t& hi, uint32_t& lo) {
    float x = __uint_as_float(xu);
    uint32_t h;
    asm("cvt.rna.tf32.f32 %0, %1;" : "=r"(h) : "f"(x));
    float lf = x - __uint_as_float(h);
    uint32_t l;
    asm("cvt.rna.tf32.f32 %0, %1;" : "=r"(l) : "f"(lf));
    hi = h; lo = l;
}
__device__ __forceinline__ void cpwait(int n) {
    if (n <= 0) asm volatile("cp.async.wait_group 0;" ::: "memory");
    else        asm volatile("cp.async.wait_group 1;" ::: "memory");
}
// stage = [A | Bhi | Blo], each 128 rows x 32 f32, SW128
__device__ __forceinline__ void ld_chunk(const float* __restrict__ A,
                                         const float* __restrict__ Whi,
                                         const float* __restrict__ Wlo, int K,
                                         int bm, int bn, int c, uint32_t stg, int tid) {
#pragma unroll
    for (int pl = 0; pl < 3; ++pl) {
        const float* base = (pl == 0) ? A + (size_t)bm * K
                          : (pl == 1) ? Whi + (size_t)bn * K
                                      : Wlo + (size_t)bn * K;
        uint32_t pbase = stg + (uint32_t)pl * CHUNK_BYTES;
#pragma unroll
        for (int it = 0; it < 4; ++it) {
            int idx = it * 256 + tid;
            int r = idx >> 3, g = idx & 7;
            const float* src = base + (size_t)r * K + (c << 5) + (g << 2);
            uint32_t dst = pbase + swz((uint32_t)(r * 128 + g * 16));
            asm volatile("cp.async.cg.shared.global [%0], [%1], 16;" :: "r"(dst), "l"(src));
        }
    }
    asm volatile("cp.async.commit_group;" ::: "memory");
}

#define MMA_TF32(cc, a0, a1, a2, a3, b0, b1) \
    asm("mma.sync.aligned.m16n8k8.row.col.f32.tf32.tf32.f32 " \
        "{%0,%1,%2,%3}, {%4,%5,%6,%7}, {%8,%9}, {%0,%1,%2,%3};" \
        : "+f"((cc)[0]), "+f"((cc)[1]), "+f"((cc)[2]), "+f"((cc)[3]) \
        : "r"(a0), "r"(a1), "r"(a2), "r"(a3), "r"(b0), "r"(b1))

// ---------------- split-tf32 (3xTF32) tensor-core GEMM ----------------
// C[M,N] = A[M,K] * W[N,K]^T (+bias)(+relu); W as precomputed hi/lo planes.
// M,N mult of 128, K mult of 32. flags: 1 = relu, 2 = row remap 516->520.
// Columns >= nsplit are routed to C2 (at col-nsplit); both outputs use leading dim ldc.
__global__ void __launch_bounds__(256) gemm_3xtf32(
    const float* __restrict__ A, const float* __restrict__ Whi,
    const float* __restrict__ Wlo,
    const float* __restrict__ bias, float* __restrict__ C, float* __restrict__ C2,
    int K, int ldc, int nsplit, int flags)
{
    extern __shared__ char smem[];
    uint32_t sb = s2u(smem);
    int tid = threadIdx.x, wid = tid >> 5, lane = tid & 31;
    int gid = lane >> 2, tig = lane & 3;
    int warp_m = wid & 3, warp_n = wid >> 2;        // 4 x 2 warp layout
    int bm = blockIdx.y * 128, bn = blockIdx.x * 128;
    const int NC = K >> 5;
    const uint32_t gmask = (uint32_t)gid << 4;

    float acc[2][8][4];
#pragma unroll
    for (int m = 0; m < 2; ++m)
#pragma unroll
        for (int n = 0; n < 8; ++n)
#pragma unroll
            for (int q = 0; q < 4; ++q) acc[m][n][q] = 0.f;

#pragma unroll
    for (int p = 0; p < STAGES; ++p)
        ld_chunk(A, Whi, Wlo, K, bm, bn, p, sb + p * STAGE_BYTES, tid);

    for (int c = 0; c < NC; ++c) {
        int s = c & 1;
        int pend = NC - 1 - c; if (pend > STAGES - 1) pend = STAGES - 1;
        cpwait(pend);
        __syncthreads();
        uint32_t aA  = sb + s * STAGE_BYTES;
        uint32_t aBh = aA + CHUNK_BYTES;
        uint32_t aBl = aA + 2 * CHUNK_BYTES;
#pragma unroll
        for (int kq = 0; kq < 4; ++kq) {
            uint32_t k4 = (uint32_t)kq * 32;
            uint32_t kx0 = (k4 ^ gmask) + (uint32_t)tig * 4;
            uint32_t kx1 = ((k4 + 16) ^ gmask) + (uint32_t)tig * 4;
            uint32_t ah[2][4], al[2][4];
#pragma unroll
            for (int m = 0; m < 2; ++m) {
                uint32_t r0 = aA + (uint32_t)(warp_m * 32 + m * 16 + gid) * 128;
                uint32_t r1 = r0 + 8 * 128;
                split_tf32(lds_u(r0 + kx0), ah[m][0], al[m][0]);
                split_tf32(lds_u(r1 + kx0), ah[m][1], al[m][1]);
                split_tf32(lds_u(r0 + kx1), ah[m][2], al[m][2]);
                split_tf32(lds_u(r1 + kx1), ah[m][3], al[m][3]);
            }
#pragma unroll
            for (int n = 0; n < 8; ++n) {
                uint32_t roff = (uint32_t)(warp_n * 64 + n * 8 + gid) * 128;
                uint32_t bh0 = lds_u(aBh + roff + kx0);
                uint32_t bh1 = lds_u(aBh + roff + kx1);
                uint32_t bl0 = lds_u(aBl + roff + kx0);
                uint32_t bl1 = lds_u(aBl + roff + kx1);
#pragma unroll
                for (int m = 0; m < 2; ++m) {
                    MMA_TF32(acc[m][n], al[m][0], al[m][1], al[m][2], al[m][3], bh0, bh1);
                    MMA_TF32(acc[m][n], ah[m][0], ah[m][1], ah[m][2], ah[m][3], bl0, bl1);
                    MMA_TF32(acc[m][n], ah[m][0], ah[m][1], ah[m][2], ah[m][3], bh0, bh1);
                }
            }
        }
        __syncthreads();
        if (c + STAGES < NC)
            ld_chunk(A, Whi, Wlo, K, bm, bn, c + STAGES, sb + s * STAGE_BYTES, tid);
    }

    // epilogue (column routing for fused outputs)
    float* Ct = C;
    int cb = bn;
    if (bn >= nsplit) { Ct = C2; cb = bn - nsplit; }
#pragma unroll
    for (int m = 0; m < 2; ++m) {
        int r0 = bm + warp_m * 32 + m * 16 + gid;
        int r1 = r0 + 8;
        int o0 = r0, o1 = r1;
        if (flags & 2) {
            int bb0 = r0 / 516; o0 = bb0 * 520 + (r0 - bb0 * 516);
            int bb1 = r1 / 516; o1 = bb1 * 520 + (r1 - bb1 * 516);
        }
#pragma unroll
        for (int n = 0; n < 8; ++n) {
            int cn0 = bn + warp_n * 64 + n * 8 + tig * 2;   // original col (bias index)
            int cnl = cb + warp_n * 64 + n * 8 + tig * 2;   // routed col
            float bx = 0.f, by = 0.f;
            if (bias) { float2 bv = *(const float2*)(bias + cn0); bx = bv.x; by = bv.y; }
            float v0 = acc[m][n][0] + bx, v1 = acc[m][n][1] + by;
            float v2 = acc[m][n][2] + bx, v3 = acc[m][n][3] + by;
            if (flags & 1) {
                v0 = fmaxf(v0, 0.f); v1 = fmaxf(v1, 0.f);
                v2 = fmaxf(v2, 0.f); v3 = fmaxf(v3, 0.f);
            }
            *(float2*)(Ct + (size_t)o0 * ldc + cnl) = make_float2(v0, v1);
            *(float2*)(Ct + (size_t)o1 * ldc + cnl) = make_float2(v2, v3);
        }
    }
}

// ---------------- weight splitting (elementwise, once) ----------------
__global__ void splitw_kernel(const float* __restrict__ s,
                              float* __restrict__ hi, float* __restrict__ lo, int n4) {
    int i = blockIdx.x * 256 + threadIdx.x;
    if (i >= n4) return;
    float4 v = ((const float4*)s)[i];
    float4 h4, l4;
    uint32_t h, l;
    split_tf32(__float_as_uint(v.x), h, l); h4.x = __uint_as_float(h); l4.x = __uint_as_float(l);
    split_tf32(__float_as_uint(v.y), h, l); h4.y = __uint_as_float(h); l4.y = __uint_as_float(l);
    split_tf32(__float_as_uint(v.z), h, l); h4.z = __uint_as_float(h); l4.z = __uint_as_float(l);
    split_tf32(__float_as_uint(v.w), h, l); h4.w = __uint_as_float(h); l4.w = __uint_as_float(l);
    ((float4*)hi)[i] = h4;
    ((float4*)lo)[i] = l4;
}

// ---------------- RevIN + tokenization ----------------
__global__ void tok_stats_kernel(const float* __restrict__ xe) {
    int b = blockIdx.y;
    int tx = threadIdx.x, ty = threadIdx.y;
    int e = blockIdx.x * 32 + tx;
    const float* p = xe + (size_t)b * LSEQ * EIN + e;
    float s = 0.f, s2 = 0.f;
    for (int l = ty; l < LSEQ; l += 8) {
        float v = p[(size_t)l * EIN];
        s += v; s2 += v * v;
    }
    __shared__ float sh[8][32], sh2[8][32], shm[32], shr[32];
    sh[ty][tx] = s; sh2[ty][tx] = s2;
    __syncthreads();
    if (ty == 0) {
        float ts = 0.f, ts2 = 0.f;
        for (int r = 0; r < 8; ++r) { ts += sh[r][tx]; ts2 += sh2[r][tx]; }
        float m = ts * (1.f / 512.f);
        float var = ts2 * (1.f / 512.f) - m * m;
        if (var < 0.f) var = 0.f;
        float sd = sqrtf(var + 1e-5f);
        g_mean[b * EIN + e] = m;
        g_std[b * EIN + e] = sd;
        shm[tx] = m; shr[tx] = 1.f / sd;
    }
    __syncthreads();
    float m = shm[tx], r = shr[tx];
    float* orow = g_attn + (size_t)(b * NTOK + e) * LSEQ;
    for (int l = ty; l < LSEQ; l += 8)
        orow[l] = (p[(size_t)l * EIN] - m) * r;
}

__global__ void marks_kernel(const float* __restrict__ xm) {
    int idx = blockIdx.x * 256 + threadIdx.x;
    if (idx >= NBB * NMARK * LSEQ) return;
    int b = idx / (NMARK * LSEQ);
    int rem = idx - b * NMARK * LSEQ;
    int j = rem / LSEQ, l = rem - j * LSEQ;
    g_attn[(size_t)(b * NTOK + EIN + j) * LSEQ + l] =
        xm[((size_t)b * LSEQ + l) * NMARK + j];
}

__global__ void zeropad_kernel() {
    int idx = blockIdx.x * 256 + threadIdx.x;
    if (idx >= NBB * 4 * DM) return;
    int b = idx / (4 * DM);
    int rem = idx - b * 4 * DM;
    int j = rem / DM, d = rem - j * DM;
    g_x[(size_t)(b * TP + NTOK + j) * DM + d] = 0.f;
}

// ---------------- LSH hashing (8 t per warp, register-blocked) ----------------
__global__ void hash_kernel(const float* __restrict__ rotl) {
    int h = blockIdx.x;
    int bh = blockIdx.y;
    int b = bh >> 3, head = bh & 7;
    __shared__ float rs[65 * 64];          // rs[f*65 + i]
    __shared__ float sq[8][8][64];         // [warp][j][f]
    int tid = threadIdx.x;
    for (int idx = tid; idx < 65 * 64; idx += 256) {
        int f = idx / 65, i = idx - f * 65;
        rs[idx] = rotl[(size_t)f * (NHASH * 65) + h * 65 + i];
    }
    __syncthreads();
    int w = tid >> 5, lane = tid & 31;
    for (int t8 = w; t8 < 65; t8 += 8) {
        int t0 = t8 * 8;
        for (int idx = lane; idx < 128; idx += 32) {
            int j = idx >> 4, f4 = idx & 15;
            const float4* qrow = (const float4*)(g_qk + (size_t)(b * TP + t0 + j) * DM + head * DHD);
            *(float4*)&sq[w][j][f4 * 4] = qrow[f4];
        }
        __syncwarp();
        float a0[8], a1[8], a2[8];
#pragma unroll
        for (int j = 0; j < 8; ++j) { a0[j] = 0.f; a1[j] = 0.f; a2[j] = 0.f; }
#pragma unroll 4
        for (int f4 = 0; f4 < 16; ++f4) {
            float4 q[8];
#pragma unroll
            for (int j = 0; j < 8; ++j) q[j] = *(const float4*)&sq[w][j][f4 * 4];
#pragma unroll
            for (int ff = 0; ff < 4; ++ff) {
                int f = f4 * 4 + ff;
                float r0 = rs[f * 65 + lane];
                float r1 = rs[f * 65 + lane + 32];
                float r2 = rs[f * 65 + 64];
#pragma unroll
                for (int j = 0; j < 8; ++j) {
                    float qv = (ff == 0) ? q[j].x : (ff == 1) ? q[j].y : (ff == 2) ? q[j].z : q[j].w;
                    a0[j] += qv * r0;
                    a1[j] += qv * r1;
                    a2[j] += qv * r2;
                }
            }
        }
#pragma unroll
        for (int j = 0; j < 8; ++j) {
            float best = a0[j]; int bidx = lane;
            float n0 = -a0[j];
            if (n0 > best || (n0 == best && lane + 65 < bidx)) { best = n0; bidx = lane + 65; }
            float d1 = a1[j]; int i1 = lane + 32;
            if (d1 > best || (d1 == best && i1 < bidx)) { best = d1; bidx = i1; }
            float n1 = -d1;
            if (n1 > best || (n1 == best && i1 + 65 < bidx)) { best = n1; bidx = i1 + 65; }
            if (lane == 0) {
                float d2 = a2[j];
                if (d2 > best || (d2 == best && 64 < bidx)) { best = d2; bidx = 64; }
                float n2 = -d2;
                if (n2 > best || (n2 == best && 129 < bidx)) { best = n2; bidx = 129; }
            }
            for (int off = 16; off; off >>= 1) {
                float ov = __shfl_xor_sync(0xffffffffu, best, off);
                int oi  = __shfl_xor_sync(0xffffffffu, bidx, off);
                if (ov > best || (ov == best && oi < bidx)) { best = ov; bidx = oi; }
            }
            if (lane == 0) g_bin[(bh * NHASH + h) * TP + t0 + j] = bidx + h * NB;
        }
        __syncwarp();
    }
}

// ---------------- stable counting sort ----------------
__global__ void sort_kernel() {
    int bh = blockIdx.x;
    int tid = threadIdx.x;
    __shared__ int cnt[NBINS], off[NBINS];
    for (int i = tid; i < NBINS; i += 256) cnt[i] = 0;
    __syncthreads();
    for (int i = tid; i < NHASH * TP; i += 256)
        atomicAdd(&cnt[g_bin[bh * (NHASH * TP) + i]], 1);
    __syncthreads();
    if (tid < 32) {
        int carry = 0;
        for (int c = 0; c < NBINS; c += 32) {
            int idx = c + tid;
            int v = (idx < NBINS) ? cnt[idx] : 0;
            int own = v;
            for (int d = 1; d < 32; d <<= 1) {
                int t2 = __shfl_up_sync(0xffffffffu, v, d);
                if (tid >= d) v += t2;
            }
            if (idx < NBINS) off[idx] = (v - own) + carry;
            carry += __shfl_sync(0xffffffffu, v, 31);
        }
    }
    __syncthreads();
    int w = tid >> 5, lane = tid & 31;
    if (w < NHASH) {
        for (int base = 0; base < TP; base += 32) {
            int pos = base + lane;
            bool act = pos < TP;
            unsigned mask = __ballot_sync(0xffffffffu, act);
            if (act) {
                int bin = g_bin[bh * (NHASH * TP) + w * TP + pos];
                unsigned peers = __match_any_sync(mask, bin);
                int leader = __ffs(peers) - 1;
                int rank = __popc(peers & ((1u << lane) - 1));
                int baseoff = 0;
                if (lane == leader) baseoff = atomicAdd(&off[bin], __popc(peers));
                baseoff = __shfl_sync(peers, baseoff, leader);
                g_stick[bh * (NHASH * TP) + baseoff + rank] = w * TP + pos;
            }
            __syncwarp();
        }
    }
}

// ---------------- chunked LSH attention (float4 gathers, grid.y=8) ----------------
__global__ void attn_kernel(int only_pos) {
    int bh = blockIdx.x;
    int b = bh >> 3, head = bh & 7;
    int tid = threadIdx.x, w = tid >> 5, lane = tid & 31;
    __shared__ float sk[8][8 * KST];
    __shared__ float sv[8][8 * KST];
    __shared__ int   sfull[8][8];
    __shared__ float srn[8][8];
    const int sbase = bh * (NHASH * TP);

    for (int c = w + 8 * blockIdx.y; c < NCH; c += 64) {
        int prev = (c + NCH - 1) % NCH;
        if (lane < 8) {
            int slot = (lane < 4) ? (c * 4 + lane) : (prev * 4 + lane - 4);
            sfull[w][lane] = g_stick[sbase + slot];
        }
        __syncwarp();
        if (only_pos >= 0) {
            bool hit = (lane < 4) && (sfull[w][lane] % TP == only_pos);
            if (!__ballot_sync(0xffffffffu, hit)) continue;
        }
        // vectorized K/V gather: 128 float4s (8 rows x 16)
#pragma unroll
        for (int it = 0; it < 4; ++it) {
            int idx = it * 32 + lane;
            int r = idx >> 4, f4 = idx & 15;
            int pos = sfull[w][r] % TP;
            size_t gbase = (size_t)(b * TP + pos) * DM + head * DHD;
            *(float4*)&sk[w][r * KST + f4 * 4] = *((const float4*)(g_qk + gbase) + f4);
            *(float4*)&sv[w][r * KST + f4 * 4] = *((const float4*)(g_v + gbase) + f4);
        }
        __syncwarp();
        if (lane < 8) {
            float ss = 0.f;
#pragma unroll 16
            for (int d = 0; d < 64; ++d) { float vv = sk[w][lane * KST + d]; ss += vv * vv; }
            srn[w][lane] = 1.f / sqrtf(fmaxf(ss, 1e-24f));
        }
        __syncwarp();
        int i = lane >> 3, j = lane & 7;
        float s = 0.f;
#pragma unroll 16
        for (int d = 0; d < 64; ++d) s += sk[w][i * KST + d] * sk[w][j * KST + d];
        s *= srn[w][j] * 0.125f;
        int fi = sfull[w][i], fj = sfull[w][j];
        if ((fi % TP) == (fj % TP)) s = -5e4f;
        float m = s;
        m = fmaxf(m, __shfl_xor_sync(0xffffffffu, m, 1, 8));
        m = fmaxf(m, __shfl_xor_sync(0xffffffffu, m, 2, 8));
        m = fmaxf(m, __shfl_xor_sync(0xffffffffu, m, 4, 8));
        float e = expf(s - m);
        float sum = e;
        sum += __shfl_xor_sync(0xffffffffu, sum, 1, 8);
        sum += __shfl_xor_sync(0xffffffffu, sum, 2, 8);
        sum += __shfl_xor_sync(0xffffffffu, sum, 4, 8);
        float lse = m + logf(sum);
        float wgt = e / sum;
        float acc[8];
#pragma unroll
        for (int d = 0; d < 8; ++d) acc[d] = 0.f;
#pragma unroll
        for (int jj = 0; jj < 8; ++jj) {
            float wj = __shfl_sync(0xffffffffu, wgt, (i << 3) | jj);
#pragma unroll
            for (int d = 0; d < 8; ++d) acc[d] += wj * sv[w][jj * KST + j * 8 + d];
        }
        int h = fi / TP, pos = fi - h * TP;
        float* op = g_ohash + (size_t)((bh * NHASH + h) * TP + pos) * DHD + j * 8;
        *(float4*)op       = make_float4(acc[0], acc[1], acc[2], acc[3]);
        *(float4*)(op + 4) = make_float4(acc[4], acc[5], acc[6], acc[7]);
        if (j == 0) g_lse[(bh * NHASH + h) * TP + pos] = lse;
        __syncwarp();
    }
}

// ---------------- combine hash rounds (8 heads per block) ----------------
__global__ void combine_kernel(int tbase) {
    int t = tbase + blockIdx.x, b = blockIdx.y;
    int tid = threadIdx.x;
    int head = tid >> 6, d = tid & 63;
    int bh = b * 8 + head;
    int base = bh * (NHASH * TP) + t;
    float l0 = g_lse[base], l1 = g_lse[base + TP];
    float l2 = g_lse[base + 2 * TP], l3 = g_lse[base + 3 * TP];
    float m = fmaxf(fmaxf(l0, l1), fmaxf(l2, l3));
    float e0 = expf(l0 - m), e1 = expf(l1 - m), e2 = expf(l2 - m), e3 = expf(l3 - m);
    float inv = 1.f / (e0 + e1 + e2 + e3);
    size_t ob = (size_t)base * DHD + d;
    size_t st = (size_t)TP * DHD;
    float acc = e0 * g_ohash[ob] + e1 * g_ohash[ob + st]
              + e2 * g_ohash[ob + 2 * st] + e3 * g_ohash[ob + 3 * st];
    g_attn[(size_t)(b * TP + t) * DM + head * DHD + d] = acc * inv;
}

// ---------------- residual + LayerNorm (full rows) ----------------
__global__ void lnadd_kernel(const float* __restrict__ gam, const float* __restrict__ bet) {
    int r = blockIdx.x;
    int b = r / NTOK, n = r - b * NTOK;
    size_t off = (size_t)(b * TP + n) * DM;
    float* xr = g_x + off;
    const float* yr = g_y + off;
    int tid = threadIdx.x;
    float v0 = xr[tid] + yr[tid];
    float v1 = xr[tid + 256] + yr[tid + 256];
    __shared__ float red[256];
    red[tid] = v0 + v1;
    __syncthreads();
    for (int s = 128; s; s >>= 1) { if (tid < s) red[tid] += red[tid + s]; __syncthreads(); }
    float mean = red[0] * (1.f / 512.f);
    __syncthreads();
    float d0 = v0 - mean, d1 = v1 - mean;
    red[tid] = d0 * d0 + d1 * d1;
    __syncthreads();
    for (int s = 128; s; s >>= 1) { if (tid < s) red[tid] += red[tid + s]; __syncthreads(); }
    float rstd = 1.f / sqrtf(red[0] * (1.f / 512.f) + 1e-5f);
    xr[tid]       = d0 * rstd * gam[tid] + bet[tid];
    xr[tid + 256] = d1 * rstd * gam[tid + 256] + bet[tid + 256];
}

// ---------------- gather token-515 rows into compact buffers ----------------
__global__ void gather_kernel() {
    int idx = blockIdx.x * 256 + threadIdx.x;
    if (idx >= 128 * DM) return;
    int r = idx >> 9, d = idx & 511;
    float a = 0.f, x = 0.f;
    if (r < NBB) {
        size_t src = (size_t)(r * TP + (NTOK - 1)) * DM + d;
        a = g_attn[src];
        x = g_x[src];
    }
    g_cattn[idx] = a;
    g_cx[idx] = x;
}

// ---------------- compact residual + LayerNorm (32 rows) ----------------
__global__ void lnadd_c_kernel(const float* __restrict__ gam, const float* __restrict__ bet) {
    size_t off = (size_t)blockIdx.x * DM;
    float* xr = g_cx + off;
    const float* yr = g_cy + off;
    int tid = threadIdx.x;
    float v0 = xr[tid] + yr[tid];
    float v1 = xr[tid + 256] + yr[tid + 256];
    __shared__ float red[256];
    red[tid] = v0 + v1;
    __syncthreads();
    for (int s = 128; s; s >>= 1) { if (tid < s) red[tid] += red[tid + s]; __syncthreads(); }
    float mean = red[0] * (1.f / 512.f);
    __syncthreads();
    float d0 = v0 - mean, d1 = v1 - mean;
    red[tid] = d0 * d0 + d1 * d1;
    __syncthreads();
    for (int s = 128; s; s >>= 1) { if (tid < s) red[tid] += red[tid + s]; __syncthreads(); }
    float rstd = 1.f / sqrtf(red[0] * (1.f / 512.f) + 1e-5f);
    xr[tid]       = d0 * rstd * gam[tid] + bet[tid];
    xr[tid + 256] = d1 * rstd * gam[tid + 256] + bet[tid + 256];
}

// ---------------- final LN + projection (compact rows) ----------------
__global__ void final_kernel(const float* __restrict__ gF, const float* __restrict__ bF,
                             const float* __restrict__ Wp, const float* __restrict__ bp) {
    int b = blockIdx.x;
    int tid = threadIdx.x;
    const float* xr = g_cx + (size_t)b * DM;
    float v = xr[tid];
    __shared__ float red[512];
    red[tid] = v; __syncthreads();
    for (int s = 256; s; s >>= 1) { if (tid < s) red[tid] += red[tid + s]; __syncthreads(); }
    float mean = red[0] * (1.f / 512.f);
    __syncthreads();
    float d = v - mean;
    red[tid] = d * d; __syncthreads();
    for (int s = 256; s; s >>= 1) { if (tid < s) red[tid] += red[tid + s]; __syncthreads(); }
    float rstd = 1.f / sqrtf(red[0] * (1.f / 512.f) + 1e-5f);
    __syncthreads();
    float nv = d * rstd * gF[tid] + bF[tid];
    red[tid] = nv * Wp[tid]; __syncthreads();
    for (int s = 256; s; s >>= 1) { if (tid < s) red[tid] += red[tid + s]; __syncthreads(); }
    if (tid == 0) g_dec[b] = red[0] + bp[0];
}

// ---------------- broadcast output ----------------
__global__ void out_kernel(float* __restrict__ out) {
    int idx = blockIdx.x * 256 + threadIdx.x;
    if (idx >= NBB * NBB * EIN) return;
    int i = idx >> 14;
    int rem = idx & 16383;
    int j = rem >> 9;
    int e = rem & 511;
    out[idx] = g_dec[j] * g_std[i * EIN + e] + g_mean[i * EIN + e];
}

// ---------------- host orchestration ----------------
static float* s_whi; static float* s_wlo;

static inline void gemm(const float* A, size_t woff, const float* bias,
                        float* C, float* C2, int M, int N, int K,
                        int ldc, int nsplit, int flags) {
    dim3 g(N / 128, M / 128), b(256);
    gemm_3xtf32<<<g, b, GEMM_SMEM>>>(A, s_whi + woff, s_wlo + woff, bias, C, C2,
                                     K, ldc, nsplit, flags);
}

extern "C" void kernel_launch(void* const* d_in, const int* in_sizes, int n_in,
                              void* d_out, int out_size) {
    (void)in_sizes; (void)n_in; (void)out_size;
    const float* x_enc  = (const float*)d_in[0];
    const float* x_mark = (const float*)d_in[1];
    const float* W_emb  = (const float*)d_in[2];
    const float* b_emb  = (const float*)d_in[3];
    const float* Wqk    = (const float*)d_in[4];
    const float* Wv     = (const float*)d_in[5];
    const float* Wo     = (const float*)d_in[6];
    const float* bo     = (const float*)d_in[7];
    const float* Wc1    = (const float*)d_in[8];
    const float* bc1    = (const float*)d_in[9];
    const float* Wc2    = (const float*)d_in[10];
    const float* bc2    = (const float*)d_in[11];
    const float* g1     = (const float*)d_in[12];
    const float* b1     = (const float*)d_in[13];
    const float* g2     = (const float*)d_in[14];
    const float* b2     = (const float*)d_in[15];
    const float* gF     = (const float*)d_in[16];
    const float* bF     = (const float*)d_in[17];
    const float* Wp     = (const float*)d_in[18];
    const float* bp     = (const float*)d_in[19];
    const float* rot    = (const float*)d_in[20];

    cudaFuncSetAttribute(gemm_3xtf32, cudaFuncAttributeMaxDynamicSharedMemorySize, GEMM_SMEM);

    float *px, *pqk, *pv, *pattn, *py, *ph, *pca, *pcx, *pcy, *pch;
    cudaGetSymbolAddress((void**)&px,    g_x);
    cudaGetSymbolAddress((void**)&pqk,   g_qk);
    cudaGetSymbolAddress((void**)&pv,    g_v);
    cudaGetSymbolAddress((void**)&pattn, g_attn);
    cudaGetSymbolAddress((void**)&py,    g_y);
    cudaGetSymbolAddress((void**)&ph,    g_h);
    cudaGetSymbolAddress((void**)&pca,   g_cattn);
    cudaGetSymbolAddress((void**)&pcx,   g_cx);
    cudaGetSymbolAddress((void**)&pcy,   g_cy);
    cudaGetSymbolAddress((void**)&pch,   g_ch);
    cudaGetSymbolAddress((void**)&s_whi, g_whi);
    cudaGetSymbolAddress((void**)&s_wlo, g_wlo);

    // split all weights into hi/lo planes; per-layer QKV rows concatenated;
    // C1/C2 both layers contiguous (src and dst) -> single launch each
    const int WQ = DM * DM;         // 262144
    const int WC = DFF * DM;        // 1048576
#define SPLW(src, dstoff, n) \
    splitw_kernel<<<((n)/4 + 255)/256, 256>>>((src), s_whi + (dstoff), s_wlo + (dstoff), (n)/4)
    SPLW(W_emb,    OFF_EMB,        WQ);
    SPLW(Wqk,      OFF_QKV0,       WQ);
    SPLW(Wv,       OFF_QKV0 + WQ,  WQ);
    SPLW(Wqk + WQ, OFF_QKV1,       WQ);
    SPLW(Wv + WQ,  OFF_QKV1 + WQ,  WQ);
    SPLW(Wo,       OFF_O0,         2 * WQ);   // both layers contiguous
    SPLW(Wc1,      OFF_C1_0,       2 * WC);   // both layers contiguous
    SPLW(Wc2,      OFF_C2_0,       2 * WC);   // both layers contiguous
#undef SPLW

    tok_stats_kernel<<<dim3(EIN / 32, NBB), dim3(32, 8)>>>(x_enc);
    marks_kernel<<<(NBB * NMARK * LSEQ + 255) / 256, 256>>>(x_mark);
    zeropad_kernel<<<(NBB * 4 * DM + 255) / 256, 256>>>();

    const int BIG = 1 << 30;
    // embedding: tok [16512,512] @ W_emb^T -> g_x (row remap to 520 stride)
    gemm(pattn, OFF_EMB, b_emb, px, nullptr, MTOK, DM, LSEQ, DM, BIG, 2);

    // ---- layer 0: full ----
    gemm(px, OFF_QKV0, nullptr, pqk, pv, MROWS, 2 * DM, DM, DM, DM, 0);  // fused QK+V
    hash_kernel<<<dim3(NHASH, BHN), 256>>>(rot);
    sort_kernel<<<BHN, 256>>>();
    attn_kernel<<<dim3(BHN, 8), 256>>>(-1);
    combine_kernel<<<dim3(TP, NBB), 512>>>(0);
    gemm(pattn, OFF_O0, bo, py, nullptr, MROWS, DM, DM, DM, BIG, 0);
    lnadd_kernel<<<MTOK, 256>>>(g1, b1);
    gemm(px, OFF_C1_0, bc1, ph, nullptr, MROWS, DFF, DM, DFF, BIG, 1);
    gemm(ph, OFF_C2_0, bc2, py, nullptr, MROWS, DM, DFF, DM, BIG, 0);
    lnadd_kernel<<<MTOK, 256>>>(g2, b2);

    // ---- layer 1: attention full, post-attention pruned to token 515 ----
    gemm(px, OFF_QKV1, nullptr, pqk, pv, MROWS, 2 * DM, DM, DM, DM, 0);  // fused QK+V
    hash_kernel<<<dim3(NHASH, BHN), 256>>>(rot + (size_t)DHD * NHASH * 65);
    sort_kernel<<<BHN, 256>>>();
    attn_kernel<<<dim3(BHN, 8), 256>>>(NTOK - 1);
    combine_kernel<<<dim3(1, NBB), 512>>>(NTOK - 1);
    gather_kernel<<<(128 * DM + 255) / 256, 256>>>();
    gemm(pca, OFF_O1, bo + DM, pcy, nullptr, 128, DM, DM, DM, BIG, 0);
    lnadd_c_kernel<<<NBB, 256>>>(g1 + DM, b1 + DM);
    gemm(pcx, OFF_C1_1, bc1 + DFF, pch, nullptr, 128, DFF, DM, DFF, BIG, 1);
    gemm(pch, OFF_C2_1, bc2 + DM, pcy, nullptr, 128, DM, DFF, DM, BIG, 0);
    lnadd_c_kernel<<<NBB, 256>>>(g2 + DM, b2 + DM);

    final_kernel<<<NBB, 512>>>(gF, bF, Wp, bp);
    out_kernel<<<(NBB * NBB * EIN + 255) / 256, 256>>>((float*)d_out);
}